// round 4
// baseline (speedup 1.0000x reference)
#include <cuda_runtime.h>
#include <cuda_bf16.h>
#include <math.h>

#define T_  12
#define M_  2048
#define B_  2
#define N_  1024
#define DIN 64
#define DH  128
#define DT  16
#define DO  32
#define NJC 8
#define CAPC 32

typedef unsigned long long u64;

// packed fp32x2 helpers (Blackwell FFMA2 path)
__device__ __forceinline__ void ffma2(u64& d, u64 a, u64 b) {
    asm("fma.rn.f32x2 %0, %1, %2, %0;" : "+l"(d) : "l"(a), "l"(b));
}
__device__ __forceinline__ void fmul2(u64& d, u64 s) {
    asm("mul.rn.f32x2 %0, %0, %1;" : "+l"(d) : "l"(s));
}
__device__ __forceinline__ u64 pack2(float x) {
    u64 r;
    unsigned u = __float_as_uint(x);
    asm("mov.b64 %0, {%1, %1};" : "=l"(r) : "r"(u));
    return r;
}
__device__ __forceinline__ float hadd2(u64 v) {
    float2 f = *(float2*)&v;
    return f.x + f.y;
}

// ---------------- device scratch ---------------
__device__ int   g_mdtype;
__device__ int   g_mask[T_ * M_];
__device__ int   g_list[T_ * M_];
__device__ int   g_mcnt[T_];
__device__ int   g_cnt8[T_ * M_ * NJC];
__device__ int   g_col [T_ * M_ * NJC * CAPC];
__device__ float g_nrm [T_ * M_];
__device__ float g_z   [T_ * M_ * DH];
__device__ float g_h   [T_ * M_ * DH];
__device__ float g_Q   [T_ * M_ * DH];
__device__ float g_K   [T_ * M_ * DH];
__device__ float g_V   [T_ * M_ * DH];
__device__ float g_agg [T_ * M_ * DH];
__device__ float g_qt  [T_ * DH];
__device__ float g_kt  [T_ * DH];
__device__ float g_vt  [T_ * DH];
__device__ float g_wc  [DH * DO];
__device__ float g_bc  [DO];

// ---------------- mask dtype detection ----------------
__global__ void k_detect(const void* p) {
    const int*   wi = (const int*)p;
    const float* wf = (const float*)p;
    int oki = 1, okf = 1;
    for (int r = 0; r < 8; r++) {
        int idx = r * 256 + threadIdx.x;
        int w  = wi[idx];
        float f = wf[idx];
        oki &= (w == 0 || w == 1);
        okf &= (f == 0.0f || f == 1.0f);
    }
    oki = __syncthreads_and(oki);
    okf = __syncthreads_and(okf);
    if (threadIdx.x == 0) g_mdtype = okf ? 2 : (oki ? 1 : 0);
}

__global__ void k_mask(const void* em) {
    int idx = blockIdx.x * 256 + threadIdx.x;
    int t = idx >> 11, m = idx & (M_ - 1);
    int b = m >> 10, n = m & (N_ - 1);
    int src = (b * T_ + t) * N_ + n;
    int dt = g_mdtype;
    int v;
    if (dt == 1)      v = ((const int*)em)[src] != 0;
    else if (dt == 2) v = ((const float*)em)[src] != 0.0f;
    else              v = ((const unsigned char*)em)[src] != 0;
    g_mask[idx] = v;
}

__global__ void __launch_bounds__(1024) k_compact() {
    int t = blockIdx.x, tid = threadIdx.x;
    __shared__ int wsum[32];
    __shared__ int sbase;
    if (tid == 0) sbase = 0;
    __syncthreads();
    for (int half = 0; half < 2; half++) {
        int i = half * 1024 + tid;
        int mv = g_mask[t * M_ + i];
        unsigned b = __ballot_sync(0xffffffffu, mv);
        int lane = tid & 31, wid = tid >> 5;
        if (lane == 0) wsum[wid] = __popc(b);
        __syncthreads();
        int woff = 0;
        for (int w = 0; w < wid; w++) woff += wsum[w];
        if (mv) g_list[t * M_ + sbase + woff + __popc(b & ((1u << lane) - 1u))] = i;
        __syncthreads();
        if (tid == 0) {
            int tot = 0;
            for (int w = 0; w < 32; w++) tot += wsum[w];
            sbase += tot;
        }
        __syncthreads();
    }
    if (tid == 0) g_mcnt[t] = sbase;
}

__global__ void k_edges(const float* __restrict__ A) {
    int t = blockIdx.x, jc = blockIdx.y, ic = blockIdx.z;
    int i = ic * 256 + threadIdx.x;
    __shared__ int mj[256];
    int jbase = jc * 256;
    mj[threadIdx.x] = g_mask[t * M_ + jbase + threadIdx.x];
    __syncthreads();
    int mi = g_mask[t * M_ + i];
    int cnt = 0;
    int* cols = g_col + ((size_t)((t * M_ + i) * NJC + jc)) * CAPC;
    if (mi) {
        const float* Ab = A + (size_t)(t * M_ + jbase) * M_ + i;
        #pragma unroll 8
        for (int jj = 0; jj < 256; jj++) {
            if (!mj[jj]) continue;              // block-uniform skip: halves A traffic
            float a = Ab[(size_t)jj * M_];
            if (a != 0.0f && cnt < CAPC) cols[cnt++] = jbase + jj;
        }
    }
    g_cnt8[(t * M_ + i) * NJC + jc] = cnt;
}

__global__ void k_nrm() {
    int idx = blockIdx.x * 256 + threadIdx.x;
    float nv = 0.0f;
    if (g_mask[idx]) {
        int c = 1;
        #pragma unroll
        for (int jc = 0; jc < NJC; jc++) c += g_cnt8[idx * NJC + jc];
        nv = rsqrtf((float)c);
    }
    g_nrm[idx] = nv;
}

__global__ void k_tbias(const float* __restrict__ tw, const float* __restrict__ tb,
                        const float* __restrict__ qw, const float* __restrict__ qb,
                        const float* __restrict__ kw, const float* __restrict__ kb,
                        const float* __restrict__ vw, const float* __restrict__ vb) {
    int t = blockIdx.x, f = threadIdx.x;
    float tv[DT];
    #pragma unroll
    for (int d = 0; d < DT; d++) tv[d] = sinf((float)t * tw[d] + tb[d]);
    float aq = qb[f], ak = kb[f], av = vb[f];
    #pragma unroll
    for (int d = 0; d < DT; d++) {
        aq += tv[d] * qw[(DH + d) * DH + f];
        ak += tv[d] * kw[(DH + d) * DH + f];
        av += tv[d] * vw[(DH + d) * DH + f];
    }
    g_qt[t * DH + f] = aq;
    g_kt[t * DH + f] = ak;
    g_vt[t * DH + f] = av;
}

__global__ void k_comb(const float* __restrict__ ow, const float* __restrict__ ob,
                       const float* __restrict__ fcw, const float* __restrict__ fcb) {
    int idx = blockIdx.x * 256 + threadIdx.x;
    int d = idx >> 5, f = idx & 31;
    float acc = 0.0f;
    #pragma unroll 8
    for (int e = 0; e < DH; e++) acc += ow[d * DH + e] * fcw[e * DO + f];
    g_wc[idx] = acc;
    if (idx < DO) {
        float b = fcb[idx];
        #pragma unroll 8
        for (int e = 0; e < DH; e++) b += ob[e] * fcw[e * DO + idx];
        g_bc[idx] = b;
    }
}

// ============ tiled GEMM: 64 nodes x 128 features, BK=32, 256 threads, FFMA2 ======
__global__ void __launch_bounds__(256) k_gemm_z(const float* __restrict__ xsrc,
                                                const float* __restrict__ W, int mode) {
    int t = blockIdx.x;
    int mc = g_mcnt[t];
    int mbase = blockIdx.y * 64;
    if (mbase >= mc) return;
    const float* src = (mode == 0) ? xsrc : (const float*)g_h;
    const int K = (mode == 0) ? DIN : DH;

    __shared__ float As[64][36];
    __shared__ float Bs[32][DH];
    __shared__ int   ridx[64];
    __shared__ float rn[64];
    int tid = threadIdx.x;
    if (tid < 64) {
        int lp = mbase + tid;
        int i = g_list[t * M_ + (lp < mc ? lp : mc - 1)];
        ridx[tid] = i;
        rn[tid] = g_nrm[t * M_ + i];
    }

    u64 acc2[4][4];
    #pragma unroll
    for (int i = 0; i < 4; i++)
        #pragma unroll
        for (int j = 0; j < 4; j++) acc2[i][j] = 0ull;
    int ty = tid >> 4, tx = tid & 15;
    int m0 = ty * 4, n0 = tx * 8;

    for (int k0 = 0; k0 < K; k0 += 32) {
        __syncthreads();
        {
            int m = tid >> 3;
            int kk = (tid & 7) * 4;
            #pragma unroll
            for (int p = 0; p < 2; p++) {
                int mm = m + p * 32;
                float4 v = *(const float4*)(src + (size_t)(t * M_ + ridx[mm]) * K + k0 + kk);
                As[mm][kk] = v.x; As[mm][kk + 1] = v.y; As[mm][kk + 2] = v.z; As[mm][kk + 3] = v.w;
            }
        }
        {
            float4* Bs4 = (float4*)Bs;
            const float4* W4 = (const float4*)(W + (size_t)k0 * DH);
            #pragma unroll
            for (int p = 0; p < 4; p++) Bs4[tid + p * 256] = W4[tid + p * 256];
        }
        __syncthreads();
        #pragma unroll
        for (int kk = 0; kk < 32; kk++) {
            u64 a0 = pack2(As[m0][kk]), a1 = pack2(As[m0 + 1][kk]);
            u64 a2 = pack2(As[m0 + 2][kk]), a3 = pack2(As[m0 + 3][kk]);
            ulonglong2 b0 = *(const ulonglong2*)&Bs[kk][n0];
            ulonglong2 b1 = *(const ulonglong2*)&Bs[kk][n0 + 4];
            ffma2(acc2[0][0], a0, b0.x); ffma2(acc2[0][1], a0, b0.y);
            ffma2(acc2[0][2], a0, b1.x); ffma2(acc2[0][3], a0, b1.y);
            ffma2(acc2[1][0], a1, b0.x); ffma2(acc2[1][1], a1, b0.y);
            ffma2(acc2[1][2], a1, b1.x); ffma2(acc2[1][3], a1, b1.y);
            ffma2(acc2[2][0], a2, b0.x); ffma2(acc2[2][1], a2, b0.y);
            ffma2(acc2[2][2], a2, b1.x); ffma2(acc2[2][3], a2, b1.y);
            ffma2(acc2[3][0], a3, b0.x); ffma2(acc2[3][1], a3, b0.y);
            ffma2(acc2[3][2], a3, b1.x); ffma2(acc2[3][3], a3, b1.y);
        }
    }
    #pragma unroll
    for (int i = 0; i < 4; i++) {
        int lp = mbase + m0 + i;
        if (lp < mc) {
            float s = rn[m0 + i];
            float* dst = g_z + (size_t)(t * M_ + ridx[m0 + i]) * DH + n0;
            float2 p0 = *(float2*)&acc2[i][0], p1 = *(float2*)&acc2[i][1];
            float2 p2 = *(float2*)&acc2[i][2], p3 = *(float2*)&acc2[i][3];
            float4 o0 = {p0.x * s, p0.y * s, p1.x * s, p1.y * s};
            float4 o1 = {p2.x * s, p2.y * s, p3.x * s, p3.y * s};
            *(float4*)dst = o0;
            *(float4*)(dst + 4) = o1;
        }
    }
}

__global__ void __launch_bounds__(256) k_gemm_qkv(const float* __restrict__ qw,
                                                  const float* __restrict__ kw,
                                                  const float* __restrict__ vw) {
    int t = blockIdx.x;
    int mc = g_mcnt[t];
    int mbase = blockIdx.y * 64;
    if (mbase >= mc) return;
    int sel = blockIdx.z;
    const float* W  = (sel == 0) ? qw : (sel == 1) ? kw : vw;
    const float* tb = (sel == 0) ? g_qt : (sel == 1) ? g_kt : g_vt;
    float* out      = (sel == 0) ? g_Q : (sel == 1) ? g_K : g_V;

    __shared__ float As[64][36];
    __shared__ float Bs[32][DH];
    __shared__ int   ridx[64];
    int tid = threadIdx.x;
    if (tid < 64) {
        int lp = mbase + tid;
        ridx[tid] = g_list[t * M_ + (lp < mc ? lp : mc - 1)];
    }
    u64 acc2[4][4];
    #pragma unroll
    for (int i = 0; i < 4; i++)
        #pragma unroll
        for (int j = 0; j < 4; j++) acc2[i][j] = 0ull;
    int ty = tid >> 4, tx = tid & 15;
    int m0 = ty * 4, n0 = tx * 8;

    for (int k0 = 0; k0 < DH; k0 += 32) {
        __syncthreads();
        {
            int m = tid >> 3;
            int kk = (tid & 7) * 4;
            #pragma unroll
            for (int p = 0; p < 2; p++) {
                int mm = m + p * 32;
                float4 v = *(const float4*)(g_h + (size_t)(t * M_ + ridx[mm]) * DH + k0 + kk);
                As[mm][kk] = v.x; As[mm][kk + 1] = v.y; As[mm][kk + 2] = v.z; As[mm][kk + 3] = v.w;
            }
        }
        {
            float4* Bs4 = (float4*)Bs;
            const float4* W4 = (const float4*)(W + (size_t)k0 * DH);
            #pragma unroll
            for (int p = 0; p < 4; p++) Bs4[tid + p * 256] = W4[tid + p * 256];
        }
        __syncthreads();
        #pragma unroll
        for (int kk = 0; kk < 32; kk++) {
            u64 a0 = pack2(As[m0][kk]), a1 = pack2(As[m0 + 1][kk]);
            u64 a2 = pack2(As[m0 + 2][kk]), a3 = pack2(As[m0 + 3][kk]);
            ulonglong2 b0 = *(const ulonglong2*)&Bs[kk][n0];
            ulonglong2 b1 = *(const ulonglong2*)&Bs[kk][n0 + 4];
            ffma2(acc2[0][0], a0, b0.x); ffma2(acc2[0][1], a0, b0.y);
            ffma2(acc2[0][2], a0, b1.x); ffma2(acc2[0][3], a0, b1.y);
            ffma2(acc2[1][0], a1, b0.x); ffma2(acc2[1][1], a1, b0.y);
            ffma2(acc2[1][2], a1, b1.x); ffma2(acc2[1][3], a1, b1.y);
            ffma2(acc2[2][0], a2, b0.x); ffma2(acc2[2][1], a2, b0.y);
            ffma2(acc2[2][2], a2, b1.x); ffma2(acc2[2][3], a2, b1.y);
            ffma2(acc2[3][0], a3, b0.x); ffma2(acc2[3][1], a3, b0.y);
            ffma2(acc2[3][2], a3, b1.x); ffma2(acc2[3][3], a3, b1.y);
        }
    }
    float4 tb0 = *(const float4*)(tb + t * DH + n0);
    float4 tb1 = *(const float4*)(tb + t * DH + n0 + 4);
    #pragma unroll
    for (int i = 0; i < 4; i++) {
        int lp = mbase + m0 + i;
        if (lp < mc) {
            float* dst = out + (size_t)(t * M_ + lp) * DH + n0;
            float2 p0 = *(float2*)&acc2[i][0], p1 = *(float2*)&acc2[i][1];
            float2 p2 = *(float2*)&acc2[i][2], p3 = *(float2*)&acc2[i][3];
            float4 o0 = {p0.x + tb0.x, p0.y + tb0.y, p1.x + tb0.z, p1.y + tb0.w};
            float4 o1 = {p2.x + tb1.x, p2.y + tb1.y, p3.x + tb1.z, p3.y + tb1.w};
            *(float4*)dst = o0;
            *(float4*)(dst + 4) = o1;
        }
    }
}

__global__ void __launch_bounds__(256) k_out2(float* __restrict__ out) {
    int t = blockIdx.x;
    int mc = g_mcnt[t];
    int mbase = blockIdx.y * 64;
    if (mbase >= mc) return;
    __shared__ float As[64][36];
    __shared__ float Ws[32][DO];
    __shared__ int   ridx[64];
    int tid = threadIdx.x;
    if (tid < 64) {
        int lp = mbase + tid;
        ridx[tid] = g_list[t * M_ + (lp < mc ? lp : mc - 1)];
    }
    float acc[4][2];
    #pragma unroll
    for (int i = 0; i < 4; i++) { acc[i][0] = 0.0f; acc[i][1] = 0.0f; }
    int ty = tid >> 4, tx = tid & 15;
    int m0 = ty * 4, n0 = tx * 2;

    for (int k0 = 0; k0 < DH; k0 += 32) {
        __syncthreads();
        {
            int m = tid >> 3;
            int kk = (tid & 7) * 4;
            #pragma unroll
            for (int p = 0; p < 2; p++) {
                int mm = m + p * 32;
                int lp = mbase + mm;
                int lpc = (lp < mc ? lp : mc - 1);
                float4 v = *(const float4*)(g_agg + (size_t)(t * M_ + lpc) * DH + k0 + kk);
                As[mm][kk] = v.x; As[mm][kk + 1] = v.y; As[mm][kk + 2] = v.z; As[mm][kk + 3] = v.w;
            }
        }
        {
            float4* Ws4 = (float4*)Ws;
            const float4* W4 = (const float4*)(g_wc + (size_t)k0 * DO);
            Ws4[tid] = W4[tid];
        }
        __syncthreads();
        #pragma unroll
        for (int kk = 0; kk < 32; kk++) {
            float a0 = As[m0][kk], a1 = As[m0 + 1][kk], a2 = As[m0 + 2][kk], a3 = As[m0 + 3][kk];
            float2 b = *(float2*)&Ws[kk][n0];
            acc[0][0] += a0 * b.x; acc[0][1] += a0 * b.y;
            acc[1][0] += a1 * b.x; acc[1][1] += a1 * b.y;
            acc[2][0] += a2 * b.x; acc[2][1] += a2 * b.y;
            acc[3][0] += a3 * b.x; acc[3][1] += a3 * b.y;
        }
    }
    float2 bc = *(const float2*)(g_bc + n0);
    #pragma unroll
    for (int i = 0; i < 4; i++) {
        int lp = mbase + m0 + i;
        if (lp < mc) {
            int node = ridx[m0 + i];
            float2 o = {acc[i][0] + bc.x, acc[i][1] + bc.y};
            *(float2*)(out + ((size_t)node * T_ + t) * DO + n0) = o;
        }
    }
}

// ---------------- sparse aggregation + bias + ReLU ----------------
__global__ void k_spmm(const float* __restrict__ bias) {
    int t = blockIdx.x, lp = blockIdx.y;
    if (lp >= g_mcnt[t]) return;
    int i = g_list[t * M_ + lp];
    int f = threadIdx.x;
    float acc = g_z[(size_t)(t * M_ + i) * DH + f];
    const int* c8 = g_cnt8 + (t * M_ + i) * NJC;
    #pragma unroll
    for (int jc = 0; jc < NJC; jc++) {
        int c = c8[jc];
        const int* cl = g_col + ((size_t)((t * M_ + i) * NJC + jc)) * CAPC;
        for (int e = 0; e < c; e++) {
            int j = cl[e];
            acc += g_z[(size_t)(t * M_ + j) * DH + f];
        }
    }
    g_h[(size_t)(t * M_ + i) * DH + f] =
        fmaxf(g_nrm[t * M_ + i] * acc + bias[f], 0.0f);
}

// ---------------- flash-style attention, conflict-free + FFMA2 ----------------
#define QT 32
#define KC 64
#define KSTR 132
#define SSTR 68
extern __shared__ float smattn[];
__global__ void __launch_bounds__(256) k_attn() {
    int t = blockIdx.x;
    int mc = g_mcnt[t];
    int qb = blockIdx.y * QT;
    if (qb >= mc) return;
    float* Qs   = smattn;
    float* Ks   = Qs + QT * DH;
    float* S    = Ks + KC * KSTR;
    float* rowm = S + QT * SSTR;
    float* rowl = rowm + QT;
    float* rowsc= rowl + QT;
    int tid = threadIdx.x;
    int nv = min(QT, mc - qb);

    #pragma unroll
    for (int p = 0; p < 4; p++) {
        int idx4 = tid + p * 256;
        int q = idx4 >> 5, d4 = (idx4 & 31) * 4;
        float4 v = {0.f, 0.f, 0.f, 0.f};
        if (q < nv) v = *(const float4*)(g_Q + (size_t)(t * M_ + qb + q) * DH + d4);
        *(float4*)(Qs + q * DH + d4) = v;
    }
    if (tid < QT) { rowm[tid] = -1e30f; rowl[tid] = 0.0f; }

    u64 pacc[8];
    #pragma unroll
    for (int j = 0; j < 8; j++) pacc[j] = 0ull;
    int q0 = (tid >> 4) * 2;
    int tx = tid & 15;
    const float scl = 0.08838834764831845f;

    for (int kb = 0; kb < mc; kb += KC) {
        int kn = min(KC, mc - kb);
        __syncthreads();
        #pragma unroll
        for (int p = 0; p < 8; p++) {
            int idx4 = tid + p * 256;
            int k = idx4 >> 5, d4 = (idx4 & 31) * 4;
            float4 v = {0.f, 0.f, 0.f, 0.f};
            if (k < kn) v = *(const float4*)(g_K + (size_t)(t * M_ + kb + k) * DH + d4);
            *(float4*)(Ks + k * KSTR + d4) = v;
        }
        __syncthreads();
        // scores: 2q x 4k, packed f32x2 FMAs
        {
            const ulonglong2* Qa = (const ulonglong2*)(Qs + q0 * DH);
            const ulonglong2* Qc = (const ulonglong2*)(Qs + (q0 + 1) * DH);
            const ulonglong2* K0 = (const ulonglong2*)(Ks + (tx     ) * KSTR);
            const ulonglong2* K1 = (const ulonglong2*)(Ks + (tx + 16) * KSTR);
            const ulonglong2* K2 = (const ulonglong2*)(Ks + (tx + 32) * KSTR);
            const ulonglong2* K3 = (const ulonglong2*)(Ks + (tx + 48) * KSTR);
            u64 a00=0,a01=0,a02=0,a03=0,a10=0,a11=0,a12=0,a13=0;
            #pragma unroll 4
            for (int d = 0; d < DH / 4; d++) {
                ulonglong2 qa = Qa[d], qc = Qc[d];
                ulonglong2 k0 = K0[d], k1 = K1[d], k2 = K2[d], k3 = K3[d];
                ffma2(a00, qa.x, k0.x); ffma2(a00, qa.y, k0.y);
                ffma2(a01, qa.x, k1.x); ffma2(a01, qa.y, k1.y);
                ffma2(a02, qa.x, k2.x); ffma2(a02, qa.y, k2.y);
                ffma2(a03, qa.x, k3.x); ffma2(a03, qa.y, k3.y);
                ffma2(a10, qc.x, k0.x); ffma2(a10, qc.y, k0.y);
                ffma2(a11, qc.x, k1.x); ffma2(a11, qc.y, k1.y);
                ffma2(a12, qc.x, k2.x); ffma2(a12, qc.y, k2.y);
                ffma2(a13, qc.x, k3.x); ffma2(a13, qc.y, k3.y);
            }
            float* S0 = S + q0 * SSTR;
            float* S1 = S0 + SSTR;
            S0[tx     ] = (tx      < kn) ? hadd2(a00) * scl : -1e30f;
            S0[tx + 16] = (tx + 16 < kn) ? hadd2(a01) * scl : -1e30f;
            S0[tx + 32] = (tx + 32 < kn) ? hadd2(a02) * scl : -1e30f;
            S0[tx + 48] = (tx + 48 < kn) ? hadd2(a03) * scl : -1e30f;
            S1[tx     ] = (tx      < kn) ? hadd2(a10) * scl : -1e30f;
            S1[tx + 16] = (tx + 16 < kn) ? hadd2(a11) * scl : -1e30f;
            S1[tx + 32] = (tx + 32 < kn) ? hadd2(a12) * scl : -1e30f;
            S1[tx + 48] = (tx + 48 < kn) ? hadd2(a13) * scl : -1e30f;
        }
        __syncthreads();
        // online softmax
        {
            int w = tid >> 5, lane = tid & 31;
            int row = w * 4 + (lane >> 3);
            int l8 = lane & 7;
            float* Sr = S + row * SSTR;
            float mloc = -1e30f;
            #pragma unroll
            for (int k = l8; k < KC; k += 8) mloc = fmaxf(mloc, Sr[k]);
            #pragma unroll
            for (int o = 4; o >= 1; o >>= 1)
                mloc = fmaxf(mloc, __shfl_xor_sync(0xffffffffu, mloc, o));
            float oldm = rowm[row];
            float newm = fmaxf(oldm, mloc);
            float ssum = 0.0f;
            #pragma unroll
            for (int k = l8; k < KC; k += 8) {
                float p = __expf(Sr[k] - newm);
                Sr[k] = p;
                ssum += p;
            }
            #pragma unroll
            for (int o = 4; o >= 1; o >>= 1)
                ssum += __shfl_xor_sync(0xffffffffu, ssum, o);
            if (l8 == 0) {
                float sc = __expf(oldm - newm);
                rowsc[row] = sc;
                rowl[row] = rowl[row] * sc + ssum;
                rowm[row] = newm;
            }
        }
        __syncthreads();
        {
            u64 sc0 = pack2(rowsc[q0]), sc1 = pack2(rowsc[q0 + 1]);
            #pragma unroll
            for (int j = 0; j < 4; j++) fmul2(pacc[j], sc0);
            #pragma unroll
            for (int j = 4; j < 8; j++) fmul2(pacc[j], sc1);
        }
        #pragma unroll
        for (int p = 0; p < 8; p++) {
            int idx4 = tid + p * 256;
            int k = idx4 >> 5, d4 = (idx4 & 31) * 4;
            float4 v = {0.f, 0.f, 0.f, 0.f};
            if (k < kn) v = *(const float4*)(g_V + (size_t)(t * M_ + kb + k) * DH + d4);
            *(float4*)(Ks + k * KSTR + d4) = v;
        }
        __syncthreads();
        // P @ V packed
        {
            const float* Sq0 = S + q0 * SSTR;
            const float* Sq1 = Sq0 + SSTR;
            for (int k = 0; k < kn; k++) {
                u64 pp0 = pack2(Sq0[k]), pp1 = pack2(Sq1[k]);
                const float* Vr = Ks + k * KSTR;
                ulonglong2 va = *(const ulonglong2*)(Vr + 4 * tx);
                ulonglong2 vb = *(const ulonglong2*)(Vr + 64 + 4 * tx);
                ffma2(pacc[0], pp0, va.x); ffma2(pacc[1], pp0, va.y);
                ffma2(pacc[2], pp0, vb.x); ffma2(pacc[3], pp0, vb.y);
                ffma2(pacc[4], pp1, va.x); ffma2(pacc[5], pp1, va.y);
                ffma2(pacc[6], pp1, vb.x); ffma2(pacc[7], pp1, vb.y);
            }
        }
    }
    __syncthreads();
    if (q0 < nv) {
        float inv = 1.0f / rowl[q0];
        float* dst = g_agg + (size_t)(t * M_ + qb + q0) * DH;
        float2 p0 = *(float2*)&pacc[0], p1 = *(float2*)&pacc[1];
        float2 p2 = *(float2*)&pacc[2], p3 = *(float2*)&pacc[3];
        float4 o0 = {p0.x * inv, p0.y * inv, p1.x * inv, p1.y * inv};
        float4 o1 = {p2.x * inv, p2.y * inv, p3.x * inv, p3.y * inv};
        *(float4*)(dst + 4 * tx) = o0;
        *(float4*)(dst + 64 + 4 * tx) = o1;
    }
    if (q0 + 1 < nv) {
        float inv = 1.0f / rowl[q0 + 1];
        float* dst = g_agg + (size_t)(t * M_ + qb + q0 + 1) * DH;
        float2 p4 = *(float2*)&pacc[4], p5 = *(float2*)&pacc[5];
        float2 p6 = *(float2*)&pacc[6], p7 = *(float2*)&pacc[7];
        float4 o0 = {p4.x * inv, p4.y * inv, p5.x * inv, p5.y * inv};
        float4 o1 = {p6.x * inv, p6.y * inv, p7.x * inv, p7.y * inv};
        *(float4*)(dst + 4 * tx) = o0;
        *(float4*)(dst + 64 + 4 * tx) = o1;
    }
}

// ---------------- launch ----------------
extern "C" void kernel_launch(void* const* d_in, const int* in_sizes, int n_in,
                              void* d_out, int out_size) {
    const float* x   = (const float*)d_in[0];
    const float* A   = (const float*)d_in[1];
    const void*  em  = d_in[2];
    const float* w1  = (const float*)d_in[3];
    const float* b1  = (const float*)d_in[4];
    const float* w2  = (const float*)d_in[5];
    const float* b2  = (const float*)d_in[6];
    const float* tw  = (const float*)d_in[7];
    const float* tb  = (const float*)d_in[8];
    const float* qw  = (const float*)d_in[9];
    const float* qb  = (const float*)d_in[10];
    const float* kw  = (const float*)d_in[11];
    const float* kb  = (const float*)d_in[12];
    const float* vw  = (const float*)d_in[13];
    const float* vb  = (const float*)d_in[14];
    const float* ow  = (const float*)d_in[15];
    const float* ob  = (const float*)d_in[16];
    const float* fcw = (const float*)d_in[17];
    const float* fcb = (const float*)d_in[18];

    static bool attr_set = false;
    const int ATTN_SMEM = (QT * DH + KC * KSTR + QT * SSTR + 3 * QT) * 4;
    if (!attr_set) {
        cudaFuncSetAttribute(k_attn, cudaFuncAttributeMaxDynamicSharedMemorySize, ATTN_SMEM);
        attr_set = true;
    }

    k_detect<<<1, 256>>>(em);
    k_mask<<<(T_ * M_) / 256, 256>>>(em);
    k_compact<<<T_, 1024>>>();
    k_edges<<<dim3(T_, NJC, M_ / 256), 256>>>(A);
    k_nrm<<<(T_ * M_) / 256, 256>>>();
    k_tbias<<<T_, DH>>>(tw, tb, qw, qb, kw, kb, vw, vb);
    k_comb<<<16, 256>>>(ow, ob, fcw, fcb);
    k_gemm_z<<<dim3(T_, M_ / 64), 256>>>(x, w1, 0);
    k_spmm<<<dim3(T_, M_), DH>>>(b1);
    k_gemm_z<<<dim3(T_, M_ / 64), 256>>>(nullptr, w2, 1);
    k_spmm<<<dim3(T_, M_), DH>>>(b2);
    k_gemm_qkv<<<dim3(T_, M_ / 64, 3), 256>>>(qw, kw, vw);
    k_attn<<<dim3(T_, M_ / QT), 256, ATTN_SMEM>>>();
    cudaMemsetAsync(d_out, 0, (size_t)out_size * sizeof(float));
    k_out2<<<dim3(T_, M_ / 64), 256>>>((float*)d_out);
}

// round 8
// speedup vs baseline: 1.0983x; 1.0983x over previous
#include <cuda_runtime.h>
#include <cuda_bf16.h>
#include <math.h>

#define T_  12
#define M_  2048
#define B_  2
#define N_  1024
#define DIN 64
#define DH  128
#define DT  16
#define DO  32
#define NJC 8
#define CAPC 32

typedef unsigned long long u64;

__device__ __forceinline__ void ffma2(u64& d, u64 a, u64 b) {
    asm("fma.rn.f32x2 %0, %1, %2, %0;" : "+l"(d) : "l"(a), "l"(b));
}
__device__ __forceinline__ void fmul2(u64& d, u64 s) {
    asm("mul.rn.f32x2 %0, %0, %1;" : "+l"(d) : "l"(s));
}
__device__ __forceinline__ u64 pack2(float x) {
    u64 r;
    unsigned u = __float_as_uint(x);
    asm("mov.b64 %0, {%1, %1};" : "=l"(r) : "r"(u));
    return r;
}
__device__ __forceinline__ float hadd2(u64 v) {
    float2 f = *(float2*)&v;
    return f.x + f.y;
}

// ---------------- device scratch ---------------
__device__ int   g_mdtype;
__device__ int   g_mask[T_ * M_];
__device__ int   g_list[T_ * M_];
__device__ int   g_mcnt[T_];
__device__ int   g_cnt8[T_ * M_ * NJC];
__device__ int   g_col [T_ * M_ * NJC * CAPC];
__device__ float g_nrm [T_ * M_];
__device__ float g_z   [T_ * M_ * DH];
__device__ float g_h   [T_ * M_ * DH];
__device__ float g_Q   [T_ * M_ * DH];
__device__ float g_K   [T_ * M_ * DH];
__device__ float g_V   [T_ * M_ * DH];
__device__ float g_agg [T_ * M_ * DH];
__device__ float g_qt  [T_ * DH];
__device__ float g_kt  [T_ * DH];
__device__ float g_vt  [T_ * DH];
__device__ float g_wc  [DH * DO];
__device__ float g_bc  [DO];

// ---------------- mask dtype detection ----------------
__global__ void k_detect(const void* p) {
    const int*   wi = (const int*)p;
    const float* wf = (const float*)p;
    int oki = 1, okf = 1;
    for (int r = 0; r < 8; r++) {
        int idx = r * 256 + threadIdx.x;
        int w  = wi[idx];
        float f = wf[idx];
        oki &= (w == 0 || w == 1);
        okf &= (f == 0.0f || f == 1.0f);
    }
    oki = __syncthreads_and(oki);
    okf = __syncthreads_and(okf);
    if (threadIdx.x == 0) g_mdtype = okf ? 2 : (oki ? 1 : 0);
}

__global__ void k_mask(const void* em) {
    int idx = blockIdx.x * 256 + threadIdx.x;
    int t = idx >> 11, m = idx & (M_ - 1);
    int b = m >> 10, n = m & (N_ - 1);
    int src = (b * T_ + t) * N_ + n;
    int dt = g_mdtype;
    int v;
    if (dt == 1)      v = ((const int*)em)[src] != 0;
    else if (dt == 2) v = ((const float*)em)[src] != 0.0f;
    else              v = ((const unsigned char*)em)[src] != 0;
    g_mask[idx] = v;
}

__global__ void __launch_bounds__(1024) k_compact() {
    int t = blockIdx.x, tid = threadIdx.x;
    __shared__ int wsum[32];
    __shared__ int sbase;
    if (tid == 0) sbase = 0;
    __syncthreads();
    for (int half = 0; half < 2; half++) {
        int i = half * 1024 + tid;
        int mv = g_mask[t * M_ + i];
        unsigned b = __ballot_sync(0xffffffffu, mv);
        int lane = tid & 31, wid = tid >> 5;
        if (lane == 0) wsum[wid] = __popc(b);
        __syncthreads();
        int woff = 0;
        for (int w = 0; w < wid; w++) woff += wsum[w];
        if (mv) g_list[t * M_ + sbase + woff + __popc(b & ((1u << lane) - 1u))] = i;
        __syncthreads();
        if (tid == 0) {
            int tot = 0;
            for (int w = 0; w < 32; w++) tot += wsum[w];
            sbase += tot;
        }
        __syncthreads();
    }
    if (tid == 0) g_mcnt[t] = sbase;
}

// streaming A scan (unconditional loads keep MLP high)
__global__ void k_edges(const float* __restrict__ A) {
    int t = blockIdx.x, jc = blockIdx.y, ic = blockIdx.z;
    int i = ic * 256 + threadIdx.x;
    __shared__ int mj[256];
    int jbase = jc * 256;
    mj[threadIdx.x] = g_mask[t * M_ + jbase + threadIdx.x];
    __syncthreads();
    int mi = g_mask[t * M_ + i];
    int cnt = 0;
    int* cols = g_col + ((size_t)((t * M_ + i) * NJC + jc)) * CAPC;
    if (mi) {
        const float* Ab = A + (size_t)(t * M_ + jbase) * M_ + i;
        #pragma unroll 8
        for (int jj = 0; jj < 256; jj++) {
            float a = Ab[(size_t)jj * M_];
            if (a != 0.0f && mj[jj] && cnt < CAPC) cols[cnt++] = jbase + jj;
        }
    }
    g_cnt8[(t * M_ + i) * NJC + jc] = cnt;
}

__global__ void k_nrm() {
    int idx = blockIdx.x * 256 + threadIdx.x;
    float nv = 0.0f;
    if (g_mask[idx]) {
        int c = 1;
        #pragma unroll
        for (int jc = 0; jc < NJC; jc++) c += g_cnt8[idx * NJC + jc];
        nv = rsqrtf((float)c);
    }
    g_nrm[idx] = nv;
}

__global__ void k_tbias(const float* __restrict__ tw, const float* __restrict__ tb,
                        const float* __restrict__ qw, const float* __restrict__ qb,
                        const float* __restrict__ kw, const float* __restrict__ kb,
                        const float* __restrict__ vw, const float* __restrict__ vb) {
    int t = blockIdx.x, f = threadIdx.x;
    float tv[DT];
    #pragma unroll
    for (int d = 0; d < DT; d++) tv[d] = sinf((float)t * tw[d] + tb[d]);
    float aq = qb[f], ak = kb[f], av = vb[f];
    #pragma unroll
    for (int d = 0; d < DT; d++) {
        aq += tv[d] * qw[(DH + d) * DH + f];
        ak += tv[d] * kw[(DH + d) * DH + f];
        av += tv[d] * vw[(DH + d) * DH + f];
    }
    g_qt[t * DH + f] = aq;
    g_kt[t * DH + f] = ak;
    g_vt[t * DH + f] = av;
}

__global__ void k_comb(const float* __restrict__ ow, const float* __restrict__ ob,
                       const float* __restrict__ fcw, const float* __restrict__ fcb) {
    int idx = blockIdx.x * 256 + threadIdx.x;
    int d = idx >> 5, f = idx & 31;
    float acc = 0.0f;
    #pragma unroll 8
    for (int e = 0; e < DH; e++) acc += ow[d * DH + e] * fcw[e * DO + f];
    g_wc[idx] = acc;
    if (idx < DO) {
        float b = fcb[idx];
        #pragma unroll 8
        for (int e = 0; e < DH; e++) b += ob[e] * fcw[e * DO + idx];
        g_bc[idx] = b;
    }
}

// ============ tiled GEMM: 64 nodes x 128 features, BK=32, 256 threads, FFMA2 ======
__global__ void __launch_bounds__(256) k_gemm_z(const float* __restrict__ xsrc,
                                                const float* __restrict__ W, int mode) {
    int t = blockIdx.x;
    int mc = g_mcnt[t];
    int mbase = blockIdx.y * 64;
    if (mbase >= mc) return;
    const float* src = (mode == 0) ? xsrc : (const float*)g_h;
    const int K = (mode == 0) ? DIN : DH;

    __shared__ float As[64][36];
    __shared__ float Bs[32][DH];
    __shared__ int   ridx[64];
    __shared__ float rn[64];
    int tid = threadIdx.x;
    if (tid < 64) {
        int lp = mbase + tid;
        int i = g_list[t * M_ + (lp < mc ? lp : mc - 1)];
        ridx[tid] = i;
        rn[tid] = g_nrm[t * M_ + i];
    }

    u64 acc2[4][4];
    #pragma unroll
    for (int i = 0; i < 4; i++)
        #pragma unroll
        for (int j = 0; j < 4; j++) acc2[i][j] = 0ull;
    int ty = tid >> 4, tx = tid & 15;
    int m0 = ty * 4, n0 = tx * 8;

    for (int k0 = 0; k0 < K; k0 += 32) {
        __syncthreads();
        {
            int m = tid >> 3;
            int kk = (tid & 7) * 4;
            #pragma unroll
            for (int p = 0; p < 2; p++) {
                int mm = m + p * 32;
                float4 v = *(const float4*)(src + (size_t)(t * M_ + ridx[mm]) * K + k0 + kk);
                As[mm][kk] = v.x; As[mm][kk + 1] = v.y; As[mm][kk + 2] = v.z; As[mm][kk + 3] = v.w;
            }
        }
        {
            float4* Bs4 = (float4*)Bs;
            const float4* W4 = (const float4*)(W + (size_t)k0 * DH);
            #pragma unroll
            for (int p = 0; p < 4; p++) Bs4[tid + p * 256] = W4[tid + p * 256];
        }
        __syncthreads();
        #pragma unroll
        for (int kk = 0; kk < 32; kk++) {
            u64 a0 = pack2(As[m0][kk]), a1 = pack2(As[m0 + 1][kk]);
            u64 a2 = pack2(As[m0 + 2][kk]), a3 = pack2(As[m0 + 3][kk]);
            ulonglong2 b0 = *(const ulonglong2*)&Bs[kk][n0];
            ulonglong2 b1 = *(const ulonglong2*)&Bs[kk][n0 + 4];
            ffma2(acc2[0][0], a0, b0.x); ffma2(acc2[0][1], a0, b0.y);
            ffma2(acc2[0][2], a0, b1.x); ffma2(acc2[0][3], a0, b1.y);
            ffma2(acc2[1][0], a1, b0.x); ffma2(acc2[1][1], a1, b0.y);
            ffma2(acc2[1][2], a1, b1.x); ffma2(acc2[1][3], a1, b1.y);
            ffma2(acc2[2][0], a2, b0.x); ffma2(acc2[2][1], a2, b0.y);
            ffma2(acc2[2][2], a2, b1.x); ffma2(acc2[2][3], a2, b1.y);
            ffma2(acc2[3][0], a3, b0.x); ffma2(acc2[3][1], a3, b0.y);
            ffma2(acc2[3][2], a3, b1.x); ffma2(acc2[3][3], a3, b1.y);
        }
    }
    #pragma unroll
    for (int i = 0; i < 4; i++) {
        int lp = mbase + m0 + i;
        if (lp < mc) {
            float s = rn[m0 + i];
            float* dst = g_z + (size_t)(t * M_ + ridx[m0 + i]) * DH + n0;
            float2 p0 = *(float2*)&acc2[i][0], p1 = *(float2*)&acc2[i][1];
            float2 p2 = *(float2*)&acc2[i][2], p3 = *(float2*)&acc2[i][3];
            float4 o0 = {p0.x * s, p0.y * s, p1.x * s, p1.y * s};
            float4 o1 = {p2.x * s, p2.y * s, p3.x * s, p3.y * s};
            *(float4*)dst = o0;
            *(float4*)(dst + 4) = o1;
        }
    }
}

__global__ void __launch_bounds__(256) k_gemm_qkv(const float* __restrict__ qw,
                                                  const float* __restrict__ kw,
                                                  const float* __restrict__ vw) {
    int t = blockIdx.x;
    int mc = g_mcnt[t];
    int mbase = blockIdx.y * 64;
    if (mbase >= mc) return;
    int sel = blockIdx.z;
    const float* W  = (sel == 0) ? qw : (sel == 1) ? kw : vw;
    const float* tb = (sel == 0) ? g_qt : (sel == 1) ? g_kt : g_vt;
    float* out      = (sel == 0) ? g_Q : (sel == 1) ? g_K : g_V;

    __shared__ float As[64][36];
    __shared__ float Bs[32][DH];
    __shared__ int   ridx[64];
    int tid = threadIdx.x;
    if (tid < 64) {
        int lp = mbase + tid;
        ridx[tid] = g_list[t * M_ + (lp < mc ? lp : mc - 1)];
    }
    u64 acc2[4][4];
    #pragma unroll
    for (int i = 0; i < 4; i++)
        #pragma unroll
        for (int j = 0; j < 4; j++) acc2[i][j] = 0ull;
    int ty = tid >> 4, tx = tid & 15;
    int m0 = ty * 4, n0 = tx * 8;

    for (int k0 = 0; k0 < DH; k0 += 32) {
        __syncthreads();
        {
            int m = tid >> 3;
            int kk = (tid & 7) * 4;
            #pragma unroll
            for (int p = 0; p < 2; p++) {
                int mm = m + p * 32;
                float4 v = *(const float4*)(g_h + (size_t)(t * M_ + ridx[mm]) * DH + k0 + kk);
                As[mm][kk] = v.x; As[mm][kk + 1] = v.y; As[mm][kk + 2] = v.z; As[mm][kk + 3] = v.w;
            }
        }
        {
            float4* Bs4 = (float4*)Bs;
            const float4* W4 = (const float4*)(W + (size_t)k0 * DH);
            #pragma unroll
            for (int p = 0; p < 4; p++) Bs4[tid + p * 256] = W4[tid + p * 256];
        }
        __syncthreads();
        #pragma unroll
        for (int kk = 0; kk < 32; kk++) {
            u64 a0 = pack2(As[m0][kk]), a1 = pack2(As[m0 + 1][kk]);
            u64 a2 = pack2(As[m0 + 2][kk]), a3 = pack2(As[m0 + 3][kk]);
            ulonglong2 b0 = *(const ulonglong2*)&Bs[kk][n0];
            ulonglong2 b1 = *(const ulonglong2*)&Bs[kk][n0 + 4];
            ffma2(acc2[0][0], a0, b0.x); ffma2(acc2[0][1], a0, b0.y);
            ffma2(acc2[0][2], a0, b1.x); ffma2(acc2[0][3], a0, b1.y);
            ffma2(acc2[1][0], a1, b0.x); ffma2(acc2[1][1], a1, b0.y);
            ffma2(acc2[1][2], a1, b1.x); ffma2(acc2[1][3], a1, b1.y);
            ffma2(acc2[2][0], a2, b0.x); ffma2(acc2[2][1], a2, b0.y);
            ffma2(acc2[2][2], a2, b1.x); ffma2(acc2[2][3], a2, b1.y);
            ffma2(acc2[3][0], a3, b0.x); ffma2(acc2[3][1], a3, b0.y);
            ffma2(acc2[3][2], a3, b1.x); ffma2(acc2[3][3], a3, b1.y);
        }
    }
    float4 tb0 = *(const float4*)(tb + t * DH + n0);
    float4 tb1 = *(const float4*)(tb + t * DH + n0 + 4);
    #pragma unroll
    for (int i = 0; i < 4; i++) {
        int lp = mbase + m0 + i;
        if (lp < mc) {
            float* dst = out + (size_t)(t * M_ + lp) * DH + n0;
            float2 p0 = *(float2*)&acc2[i][0], p1 = *(float2*)&acc2[i][1];
            float2 p2 = *(float2*)&acc2[i][2], p3 = *(float2*)&acc2[i][3];
            float4 o0 = {p0.x + tb0.x, p0.y + tb0.y, p1.x + tb0.z, p1.y + tb0.w};
            float4 o1 = {p2.x + tb1.x, p2.y + tb1.y, p3.x + tb1.z, p3.y + tb1.w};
            *(float4*)dst = o0;
            *(float4*)(dst + 4) = o1;
        }
    }
}

__global__ void __launch_bounds__(256) k_out2(float* __restrict__ out) {
    int t = blockIdx.x;
    int mc = g_mcnt[t];
    int mbase = blockIdx.y * 64;
    if (mbase >= mc) return;
    __shared__ float As[64][36];
    __shared__ float Ws[32][DO];
    __shared__ int   ridx[64];
    int tid = threadIdx.x;
    if (tid < 64) {
        int lp = mbase + tid;
        ridx[tid] = g_list[t * M_ + (lp < mc ? lp : mc - 1)];
    }
    float acc[4][2];
    #pragma unroll
    for (int i = 0; i < 4; i++) { acc[i][0] = 0.0f; acc[i][1] = 0.0f; }
    int ty = tid >> 4, tx = tid & 15;
    int m0 = ty * 4, n0 = tx * 2;

    for (int k0 = 0; k0 < DH; k0 += 32) {
        __syncthreads();
        {
            int m = tid >> 3;
            int kk = (tid & 7) * 4;
            #pragma unroll
            for (int p = 0; p < 2; p++) {
                int mm = m + p * 32;
                int lp = mbase + mm;
                int lpc = (lp < mc ? lp : mc - 1);
                float4 v = *(const float4*)(g_agg + (size_t)(t * M_ + lpc) * DH + k0 + kk);
                As[mm][kk] = v.x; As[mm][kk + 1] = v.y; As[mm][kk + 2] = v.z; As[mm][kk + 3] = v.w;
            }
        }
        {
            float4* Ws4 = (float4*)Ws;
            const float4* W4 = (const float4*)(g_wc + (size_t)k0 * DO);
            Ws4[tid] = W4[tid];
        }
        __syncthreads();
        #pragma unroll
        for (int kk = 0; kk < 32; kk++) {
            float a0 = As[m0][kk], a1 = As[m0 + 1][kk], a2 = As[m0 + 2][kk], a3 = As[m0 + 3][kk];
            float2 b = *(float2*)&Ws[kk][n0];
            acc[0][0] += a0 * b.x; acc[0][1] += a0 * b.y;
            acc[1][0] += a1 * b.x; acc[1][1] += a1 * b.y;
            acc[2][0] += a2 * b.x; acc[2][1] += a2 * b.y;
            acc[3][0] += a3 * b.x; acc[3][1] += a3 * b.y;
        }
    }
    float2 bc = *(const float2*)(g_bc + n0);
    #pragma unroll
    for (int i = 0; i < 4; i++) {
        int lp = mbase + m0 + i;
        if (lp < mc) {
            int node = ridx[m0 + i];
            float2 o = {acc[i][0] + bc.x, acc[i][1] + bc.y};
            *(float2*)(out + ((size_t)node * T_ + t) * DO + n0) = o;
        }
    }
}

// ---------------- sparse aggregation + bias + ReLU ----------------
__global__ void k_spmm(const float* __restrict__ bias) {
    int t = blockIdx.x, lp = blockIdx.y;
    if (lp >= g_mcnt[t]) return;
    int i = g_list[t * M_ + lp];
    int f = threadIdx.x;
    float acc = g_z[(size_t)(t * M_ + i) * DH + f];
    const int* c8 = g_cnt8 + (t * M_ + i) * NJC;
    #pragma unroll
    for (int jc = 0; jc < NJC; jc++) {
        int c = c8[jc];
        const int* cl = g_col + ((size_t)((t * M_ + i) * NJC + jc)) * CAPC;
        for (int e = 0; e < c; e++) {
            int j = cl[e];
            acc += g_z[(size_t)(t * M_ + j) * DH + f];
        }
    }
    g_h[(size_t)(t * M_ + i) * DH + f] =
        fmaxf(g_nrm[t * M_ + i] * acc + bias[f], 0.0f);
}

// ---------------- flash attention: QT=64, 4q x 4k micro-tile, FFMA2 ----------------
#define QT 64
#define KC 64
#define KSTR 132
#define SSTR 68
extern __shared__ float smattn[];
__global__ void __launch_bounds__(256) k_attn() {
    int t = blockIdx.x;
    int mc = g_mcnt[t];
    int qb = blockIdx.y * QT;
    if (qb >= mc) return;
    float* Qs   = smattn;                 // QT*DH
    float* Ks   = Qs + QT * DH;           // KC*KSTR (reused for V)
    float* S    = Ks + KC * KSTR;         // QT*SSTR
    float* rowm = S + QT * SSTR;          // QT
    float* rowl = rowm + QT;
    float* rowsc= rowl + QT;
    int tid = threadIdx.x;
    int nv = min(QT, mc - qb);

    // Q fill: QT*DH/4 = 2048 float4
    for (int p = 0; p < 8; p++) {
        int idx4 = tid + p * 256;
        int q = idx4 >> 5, d4 = (idx4 & 31) * 4;
        float4 v = {0.f, 0.f, 0.f, 0.f};
        if (q < nv) v = *(const float4*)(g_Q + (size_t)(t * M_ + qb + q) * DH + d4);
        *(float4*)(Qs + q * DH + d4) = v;
    }
    if (tid < QT) { rowm[tid] = -1e30f; rowl[tid] = 0.0f; }

    u64 pacc[16];                         // 4 q rows x 8 floats
    #pragma unroll
    for (int j = 0; j < 16; j++) pacc[j] = 0ull;
    int q0 = (tid >> 4) * 4;              // 0..60
    int tx = tid & 15;
    const float scl = 0.08838834764831845f;

    for (int kb = 0; kb < mc; kb += KC) {
        int kn = min(KC, mc - kb);
        __syncthreads();
        for (int p = 0; p < 8; p++) {
            int idx4 = tid + p * 256;
            int k = idx4 >> 5, d4 = (idx4 & 31) * 4;
            float4 v = {0.f, 0.f, 0.f, 0.f};
            if (k < kn) v = *(const float4*)(g_K + (size_t)(t * M_ + kb + k) * DH + d4);
            *(float4*)(Ks + k * KSTR + d4) = v;
        }
        __syncthreads();
        // scores: 4q x 4k per thread
        {
            const ulonglong2* Q0 = (const ulonglong2*)(Qs + (q0    ) * DH);
            const ulonglong2* Q1 = (const ulonglong2*)(Qs + (q0 + 1) * DH);
            const ulonglong2* Q2 = (const ulonglong2*)(Qs + (q0 + 2) * DH);
            const ulonglong2* Q3 = (const ulonglong2*)(Qs + (q0 + 3) * DH);
            const ulonglong2* K0 = (const ulonglong2*)(Ks + (tx     ) * KSTR);
            const ulonglong2* K1 = (const ulonglong2*)(Ks + (tx + 16) * KSTR);
            const ulonglong2* K2 = (const ulonglong2*)(Ks + (tx + 32) * KSTR);
            const ulonglong2* K3 = (const ulonglong2*)(Ks + (tx + 48) * KSTR);
            u64 a[4][4];
            #pragma unroll
            for (int i = 0; i < 4; i++)
                #pragma unroll
                for (int j = 0; j < 4; j++) a[i][j] = 0ull;
            for (int d = 0; d < DH / 4; d++) {
                ulonglong2 k0 = K0[d], k1 = K1[d], k2 = K2[d], k3 = K3[d];
                ulonglong2 q;
                q = Q0[d];
                ffma2(a[0][0], q.x, k0.x); ffma2(a[0][0], q.y, k0.y);
                ffma2(a[0][1], q.x, k1.x); ffma2(a[0][1], q.y, k1.y);
                ffma2(a[0][2], q.x, k2.x); ffma2(a[0][2], q.y, k2.y);
                ffma2(a[0][3], q.x, k3.x); ffma2(a[0][3], q.y, k3.y);
                q = Q1[d];
                ffma2(a[1][0], q.x, k0.x); ffma2(a[1][0], q.y, k0.y);
                ffma2(a[1][1], q.x, k1.x); ffma2(a[1][1], q.y, k1.y);
                ffma2(a[1][2], q.x, k2.x); ffma2(a[1][2], q.y, k2.y);
                ffma2(a[1][3], q.x, k3.x); ffma2(a[1][3], q.y, k3.y);
                q = Q2[d];
                ffma2(a[2][0], q.x, k0.x); ffma2(a[2][0], q.y, k0.y);
                ffma2(a[2][1], q.x, k1.x); ffma2(a[2][1], q.y, k1.y);
                ffma2(a[2][2], q.x, k2.x); ffma2(a[2][2], q.y, k2.y);
                ffma2(a[2][3], q.x, k3.x); ffma2(a[2][3], q.y, k3.y);
                q = Q3[d];
                ffma2(a[3][0], q.x, k0.x); ffma2(a[3][0], q.y, k0.y);
                ffma2(a[3][1], q.x, k1.x); ffma2(a[3][1], q.y, k1.y);
                ffma2(a[3][2], q.x, k2.x); ffma2(a[3][2], q.y, k2.y);
                ffma2(a[3][3], q.x, k3.x); ffma2(a[3][3], q.y, k3.y);
            }
            #pragma unroll
            for (int i = 0; i < 4; i++) {
                float* Si = S + (q0 + i) * SSTR;
                Si[tx     ] = (tx      < kn) ? hadd2(a[i][0]) * scl : -1e30f;
                Si[tx + 16] = (tx + 16 < kn) ? hadd2(a[i][1]) * scl : -1e30f;
                Si[tx + 32] = (tx + 32 < kn) ? hadd2(a[i][2]) * scl : -1e30f;
                Si[tx + 48] = (tx + 48 < kn) ? hadd2(a[i][3]) * scl : -1e30f;
            }
        }
        __syncthreads();
        // online softmax: 8 warps x 8 rows, 4 lanes per row
        {
            int w = tid >> 5, lane = tid & 31;
            int row = w * 8 + (lane >> 2);
            int l4 = lane & 3;
            float* Sr = S + row * SSTR;
            float mloc = -1e30f;
            for (int k = l4; k < KC; k += 4) mloc = fmaxf(mloc, Sr[k]);
            #pragma unroll
            for (int o = 2; o >= 1; o >>= 1)
                mloc = fmaxf(mloc, __shfl_xor_sync(0xffffffffu, mloc, o));
            float oldm = rowm[row];
            float newm = fmaxf(oldm, mloc);
            float ssum = 0.0f;
            for (int k = l4; k < KC; k += 4) {
                float p = __expf(Sr[k] - newm);
                Sr[k] = p;
                ssum += p;
            }
            #pragma unroll
            for (int o = 2; o >= 1; o >>= 1)
                ssum += __shfl_xor_sync(0xffffffffu, ssum, o);
            if (l4 == 0) {
                float sc = __expf(oldm - newm);
                rowsc[row] = sc;
                rowl[row] = rowl[row] * sc + ssum;
                rowm[row] = newm;
            }
        }
        __syncthreads();
        {
            #pragma unroll
            for (int i = 0; i < 4; i++) {
                u64 sc = pack2(rowsc[q0 + i]);
                fmul2(pacc[i * 4 + 0], sc); fmul2(pacc[i * 4 + 1], sc);
                fmul2(pacc[i * 4 + 2], sc); fmul2(pacc[i * 4 + 3], sc);
            }
        }
        // V fill (reuses Ks)
        for (int p = 0; p < 8; p++) {
            int idx4 = tid + p * 256;
            int k = idx4 >> 5, d4 = (idx4 & 31) * 4;
            float4 v = {0.f, 0.f, 0.f, 0.f};
            if (k < kn) v = *(const float4*)(g_V + (size_t)(t * M_ + kb + k) * DH + d4);
            *(float4*)(Ks + k * KSTR + d4) = v;
        }
        __syncthreads();
        // P @ V: 4 q rows share each V row
        {
            const float* S0 = S + (q0    ) * SSTR;
            const float* S1 = S + (q0 + 1) * SSTR;
            const float* S2 = S + (q0 + 2) * SSTR;
            const float* S3 = S + (q0 + 3) * SSTR;
            for (int k = 0; k < kn; k++) {
                const float* Vr = Ks + k * KSTR;
                ulonglong2 va = *(const ulonglong2*)(Vr + 4 * tx);
                ulonglong2 vb = *(const ulonglong2*)(Vr + 64 + 4 * tx);
                u64 pp;
                pp = pack2(S0[k]);
                ffma2(pacc[0], pp, va.x); ffma2(pacc[1], pp, va.y);
                ffma2(pacc[2], pp, vb.x); ffma2(pacc[3], pp, vb.y);
                pp = pack2(S1[k]);
                ffma2(pacc[4], pp, va.x); ffma2(pacc[5], pp, va.y);
                ffma2(pacc[6], pp, vb.x); ffma2(pacc[7], pp, vb.y);
                pp = pack2(S2[k]);
                ffma2(pacc[8], pp, va.x); ffma2(pacc[9], pp, va.y);
                ffma2(pacc[10], pp, vb.x); ffma2(pacc[11], pp, vb.y);
                pp = pack2(S3[k]);
                ffma2(pacc[12], pp, va.x); ffma2(pacc[13], pp, va.y);
                ffma2(pacc[14], pp, vb.x); ffma2(pacc[15], pp, vb.y);
            }
        }
    }
    __syncthreads();
    #pragma unroll
    for (int i = 0; i < 4; i++) {
        if (q0 + i < nv) {
            float inv = 1.0f / rowl[q0 + i];
            float* dst = g_agg + (size_t)(t * M_ + qb + q0 + i) * DH;
            float2 p0 = *(float2*)&pacc[i*4+0], p1 = *(float2*)&pacc[i*4+1];
            float2 p2 = *(float2*)&pacc[i*4+2], p3 = *(float2*)&pacc[i*4+3];
            float4 o0 = {p0.x * inv, p0.y * inv, p1.x * inv, p1.y * inv};
            float4 o1 = {p2.x * inv, p2.y * inv, p3.x * inv, p3.y * inv};
            *(float4*)(dst + 4 * tx) = o0;
            *(float4*)(dst + 64 + 4 * tx) = o1;
        }
    }
}

// ---------------- launch ----------------
extern "C" void kernel_launch(void* const* d_in, const int* in_sizes, int n_in,
                              void* d_out, int out_size) {
    const float* x   = (const float*)d_in[0];
    const float* A   = (const float*)d_in[1];
    const void*  em  = d_in[2];
    const float* w1  = (const float*)d_in[3];
    const float* b1  = (const float*)d_in[4];
    const float* w2  = (const float*)d_in[5];
    const float* b2  = (const float*)d_in[6];
    const float* tw  = (const float*)d_in[7];
    const float* tb  = (const float*)d_in[8];
    const float* qw  = (const float*)d_in[9];
    const float* qb  = (const float*)d_in[10];
    const float* kw  = (const float*)d_in[11];
    const float* kb  = (const float*)d_in[12];
    const float* vw  = (const float*)d_in[13];
    const float* vb  = (const float*)d_in[14];
    const float* ow  = (const float*)d_in[15];
    const float* ob  = (const float*)d_in[16];
    const float* fcw = (const float*)d_in[17];
    const float* fcb = (const float*)d_in[18];

    const int ATTN_SMEM = (QT * DH + KC * KSTR + QT * SSTR + 3 * QT) * 4; // 84736 B
    cudaFuncSetAttribute(k_attn, cudaFuncAttributeMaxDynamicSharedMemorySize, ATTN_SMEM);

    k_detect<<<1, 256>>>(em);
    k_mask<<<(T_ * M_) / 256, 256>>>(em);
    k_compact<<<T_, 1024>>>();
    k_edges<<<dim3(T_, NJC, M_ / 256), 256>>>(A);
    k_nrm<<<(T_ * M_) / 256, 256>>>();
    k_tbias<<<T_, DH>>>(tw, tb, qw, qb, kw, kb, vw, vb);
    k_comb<<<16, 256>>>(ow, ob, fcw, fcb);
    k_gemm_z<<<dim3(T_, M_ / 64), 256>>>(x, w1, 0);
    k_spmm<<<dim3(T_, M_), DH>>>(b1);
    k_gemm_z<<<dim3(T_, M_ / 64), 256>>>(nullptr, w2, 1);
    k_spmm<<<dim3(T_, M_), DH>>>(b2);
    k_gemm_qkv<<<dim3(T_, M_ / 64, 3), 256>>>(qw, kw, vw);
    k_attn<<<dim3(T_, M_ / QT), 256, ATTN_SMEM>>>();
    cudaMemsetAsync(d_out, 0, (size_t)out_size * sizeof(float));
    k_out2<<<dim3(T_, M_ / 64), 256>>>((float*)d_out);
}

// round 9
// speedup vs baseline: 1.5072x; 1.3723x over previous
#include <cuda_runtime.h>
#include <cuda_bf16.h>
#include <math.h>

#define T_  12
#define M_  2048
#define B_  2
#define N_  1024
#define DIN 64
#define DH  128
#define DT  16
#define DO  32
#define NJC 8
#define CAPC 32

typedef unsigned long long u64;

__device__ __forceinline__ void ffma2(u64& d, u64 a, u64 b) {
    asm("fma.rn.f32x2 %0, %1, %2, %0;" : "+l"(d) : "l"(a), "l"(b));
}
__device__ __forceinline__ u64 pack2(float x) {
    u64 r;
    unsigned u = __float_as_uint(x);
    asm("mov.b64 %0, {%1, %1};" : "=l"(r) : "r"(u));
    return r;
}

// tf32 helpers
__device__ __forceinline__ float cvt_tf32(float f) {
    unsigned r;
    asm("cvt.rna.tf32.f32 %0, %1;" : "=r"(r) : "f"(f));
    return __uint_as_float(r);
}
__device__ __forceinline__ float4 cvt_tf32_4(float4 v) {
    v.x = cvt_tf32(v.x); v.y = cvt_tf32(v.y);
    v.z = cvt_tf32(v.z); v.w = cvt_tf32(v.w);
    return v;
}
__device__ __forceinline__ void mma_tf32(float* c,
                                         unsigned a0, unsigned a1, unsigned a2, unsigned a3,
                                         unsigned b0, unsigned b1) {
    asm("mma.sync.aligned.m16n8k8.row.col.f32.tf32.tf32.f32 "
        "{%0,%1,%2,%3}, {%4,%5,%6,%7}, {%8,%9}, {%0,%1,%2,%3};"
        : "+f"(c[0]), "+f"(c[1]), "+f"(c[2]), "+f"(c[3])
        : "r"(a0), "r"(a1), "r"(a2), "r"(a3), "r"(b0), "r"(b1));
}

// ---------------- device scratch ---------------
__device__ int   g_mdtype;
__device__ int   g_mask[T_ * M_];
__device__ int   g_list[T_ * M_];
__device__ int   g_mcnt[T_];
__device__ int   g_cnt8[T_ * M_ * NJC];
__device__ int   g_col [T_ * M_ * NJC * CAPC];
__device__ float g_nrm [T_ * M_];
__device__ float g_z   [T_ * M_ * DH];
__device__ float g_h   [T_ * M_ * DH];
__device__ float g_Q   [T_ * M_ * DH];
__device__ float g_K   [T_ * M_ * DH];
__device__ float g_V   [T_ * M_ * DH];
__device__ float g_agg [T_ * M_ * DH];
__device__ float g_qt  [T_ * DH];
__device__ float g_kt  [T_ * DH];
__device__ float g_vt  [T_ * DH];
__device__ float g_wc  [DH * DO];
__device__ float g_bc  [DO];

// ---------------- mask dtype detection ----------------
__global__ void k_detect(const void* p) {
    const int*   wi = (const int*)p;
    const float* wf = (const float*)p;
    int oki = 1, okf = 1;
    for (int r = 0; r < 8; r++) {
        int idx = r * 256 + threadIdx.x;
        int w  = wi[idx];
        float f = wf[idx];
        oki &= (w == 0 || w == 1);
        okf &= (f == 0.0f || f == 1.0f);
    }
    oki = __syncthreads_and(oki);
    okf = __syncthreads_and(okf);
    if (threadIdx.x == 0) g_mdtype = okf ? 2 : (oki ? 1 : 0);
}

__global__ void k_mask(const void* em) {
    int idx = blockIdx.x * 256 + threadIdx.x;
    int t = idx >> 11, m = idx & (M_ - 1);
    int b = m >> 10, n = m & (N_ - 1);
    int src = (b * T_ + t) * N_ + n;
    int dt = g_mdtype;
    int v;
    if (dt == 1)      v = ((const int*)em)[src] != 0;
    else if (dt == 2) v = ((const float*)em)[src] != 0.0f;
    else              v = ((const unsigned char*)em)[src] != 0;
    g_mask[idx] = v;
}

__global__ void __launch_bounds__(1024) k_compact() {
    int t = blockIdx.x, tid = threadIdx.x;
    __shared__ int wsum[32];
    __shared__ int sbase;
    if (tid == 0) sbase = 0;
    __syncthreads();
    for (int half = 0; half < 2; half++) {
        int i = half * 1024 + tid;
        int mv = g_mask[t * M_ + i];
        unsigned b = __ballot_sync(0xffffffffu, mv);
        int lane = tid & 31, wid = tid >> 5;
        if (lane == 0) wsum[wid] = __popc(b);
        __syncthreads();
        int woff = 0;
        for (int w = 0; w < wid; w++) woff += wsum[w];
        if (mv) g_list[t * M_ + sbase + woff + __popc(b & ((1u << lane) - 1u))] = i;
        __syncthreads();
        if (tid == 0) {
            int tot = 0;
            for (int w = 0; w < 32; w++) tot += wsum[w];
            sbase += tot;
        }
        __syncthreads();
    }
    if (tid == 0) g_mcnt[t] = sbase;
}

// streaming A scan (unconditional loads keep MLP high)
__global__ void k_edges(const float* __restrict__ A) {
    int t = blockIdx.x, jc = blockIdx.y, ic = blockIdx.z;
    int i = ic * 256 + threadIdx.x;
    __shared__ int mj[256];
    int jbase = jc * 256;
    mj[threadIdx.x] = g_mask[t * M_ + jbase + threadIdx.x];
    __syncthreads();
    int mi = g_mask[t * M_ + i];
    int cnt = 0;
    int* cols = g_col + ((size_t)((t * M_ + i) * NJC + jc)) * CAPC;
    if (mi) {
        const float* Ab = A + (size_t)(t * M_ + jbase) * M_ + i;
        #pragma unroll 8
        for (int jj = 0; jj < 256; jj++) {
            float a = Ab[(size_t)jj * M_];
            if (a != 0.0f && mj[jj] && cnt < CAPC) cols[cnt++] = jbase + jj;
        }
    }
    g_cnt8[(t * M_ + i) * NJC + jc] = cnt;
}

__global__ void k_nrm() {
    int idx = blockIdx.x * 256 + threadIdx.x;
    float nv = 0.0f;
    if (g_mask[idx]) {
        int c = 1;
        #pragma unroll
        for (int jc = 0; jc < NJC; jc++) c += g_cnt8[idx * NJC + jc];
        nv = rsqrtf((float)c);
    }
    g_nrm[idx] = nv;
}

__global__ void k_tbias(const float* __restrict__ tw, const float* __restrict__ tb,
                        const float* __restrict__ qw, const float* __restrict__ qb,
                        const float* __restrict__ kw, const float* __restrict__ kb,
                        const float* __restrict__ vw, const float* __restrict__ vb) {
    int t = blockIdx.x, f = threadIdx.x;
    float tv[DT];
    #pragma unroll
    for (int d = 0; d < DT; d++) tv[d] = sinf((float)t * tw[d] + tb[d]);
    float aq = qb[f], ak = kb[f], av = vb[f];
    #pragma unroll
    for (int d = 0; d < DT; d++) {
        aq += tv[d] * qw[(DH + d) * DH + f];
        ak += tv[d] * kw[(DH + d) * DH + f];
        av += tv[d] * vw[(DH + d) * DH + f];
    }
    g_qt[t * DH + f] = aq;
    g_kt[t * DH + f] = ak;
    g_vt[t * DH + f] = av;
}

__global__ void k_comb(const float* __restrict__ ow, const float* __restrict__ ob,
                       const float* __restrict__ fcw, const float* __restrict__ fcb) {
    int idx = blockIdx.x * 256 + threadIdx.x;
    int d = idx >> 5, f = idx & 31;
    float acc = 0.0f;
    #pragma unroll 8
    for (int e = 0; e < DH; e++) acc += ow[d * DH + e] * fcw[e * DO + f];
    g_wc[idx] = acc;
    if (idx < DO) {
        float b = fcb[idx];
        #pragma unroll 8
        for (int e = 0; e < DH; e++) b += ob[e] * fcw[e * DO + idx];
        g_bc[idx] = b;
    }
}

// ============ tiled GEMM: 64 nodes x 128 features, BK=32, 256 threads, FFMA2 ======
__global__ void __launch_bounds__(256) k_gemm_z(const float* __restrict__ xsrc,
                                                const float* __restrict__ W, int mode) {
    int t = blockIdx.x;
    int mc = g_mcnt[t];
    int mbase = blockIdx.y * 64;
    if (mbase >= mc) return;
    const float* src = (mode == 0) ? xsrc : (const float*)g_h;
    const int K = (mode == 0) ? DIN : DH;

    __shared__ float As[64][36];
    __shared__ float Bs[32][DH];
    __shared__ int   ridx[64];
    __shared__ float rn[64];
    int tid = threadIdx.x;
    if (tid < 64) {
        int lp = mbase + tid;
        int i = g_list[t * M_ + (lp < mc ? lp : mc - 1)];
        ridx[tid] = i;
        rn[tid] = g_nrm[t * M_ + i];
    }

    u64 acc2[4][4];
    #pragma unroll
    for (int i = 0; i < 4; i++)
        #pragma unroll
        for (int j = 0; j < 4; j++) acc2[i][j] = 0ull;
    int ty = tid >> 4, tx = tid & 15;
    int m0 = ty * 4, n0 = tx * 8;

    for (int k0 = 0; k0 < K; k0 += 32) {
        __syncthreads();
        {
            int m = tid >> 3;
            int kk = (tid & 7) * 4;
            #pragma unroll
            for (int p = 0; p < 2; p++) {
                int mm = m + p * 32;
                float4 v = *(const float4*)(src + (size_t)(t * M_ + ridx[mm]) * K + k0 + kk);
                As[mm][kk] = v.x; As[mm][kk + 1] = v.y; As[mm][kk + 2] = v.z; As[mm][kk + 3] = v.w;
            }
        }
        {
            float4* Bs4 = (float4*)Bs;
            const float4* W4 = (const float4*)(W + (size_t)k0 * DH);
            #pragma unroll
            for (int p = 0; p < 4; p++) Bs4[tid + p * 256] = W4[tid + p * 256];
        }
        __syncthreads();
        #pragma unroll
        for (int kk = 0; kk < 32; kk++) {
            u64 a0 = pack2(As[m0][kk]), a1 = pack2(As[m0 + 1][kk]);
            u64 a2 = pack2(As[m0 + 2][kk]), a3 = pack2(As[m0 + 3][kk]);
            ulonglong2 b0 = *(const ulonglong2*)&Bs[kk][n0];
            ulonglong2 b1 = *(const ulonglong2*)&Bs[kk][n0 + 4];
            ffma2(acc2[0][0], a0, b0.x); ffma2(acc2[0][1], a0, b0.y);
            ffma2(acc2[0][2], a0, b1.x); ffma2(acc2[0][3], a0, b1.y);
            ffma2(acc2[1][0], a1, b0.x); ffma2(acc2[1][1], a1, b0.y);
            ffma2(acc2[1][2], a1, b1.x); ffma2(acc2[1][3], a1, b1.y);
            ffma2(acc2[2][0], a2, b0.x); ffma2(acc2[2][1], a2, b0.y);
            ffma2(acc2[2][2], a2, b1.x); ffma2(acc2[2][3], a2, b1.y);
            ffma2(acc2[3][0], a3, b0.x); ffma2(acc2[3][1], a3, b0.y);
            ffma2(acc2[3][2], a3, b1.x); ffma2(acc2[3][3], a3, b1.y);
        }
    }
    #pragma unroll
    for (int i = 0; i < 4; i++) {
        int lp = mbase + m0 + i;
        if (lp < mc) {
            float s = rn[m0 + i];
            float* dst = g_z + (size_t)(t * M_ + ridx[m0 + i]) * DH + n0;
            float2 p0 = *(float2*)&acc2[i][0], p1 = *(float2*)&acc2[i][1];
            float2 p2 = *(float2*)&acc2[i][2], p3 = *(float2*)&acc2[i][3];
            float4 o0 = {p0.x * s, p0.y * s, p1.x * s, p1.y * s};
            float4 o1 = {p2.x * s, p2.y * s, p3.x * s, p3.y * s};
            *(float4*)dst = o0;
            *(float4*)(dst + 4) = o1;
        }
    }
}

__global__ void __launch_bounds__(256) k_gemm_qkv(const float* __restrict__ qw,
                                                  const float* __restrict__ kw,
                                                  const float* __restrict__ vw) {
    int t = blockIdx.x;
    int mc = g_mcnt[t];
    int mbase = blockIdx.y * 64;
    if (mbase >= mc) return;
    int sel = blockIdx.z;
    const float* W  = (sel == 0) ? qw : (sel == 1) ? kw : vw;
    const float* tb = (sel == 0) ? g_qt : (sel == 1) ? g_kt : g_vt;
    float* out      = (sel == 0) ? g_Q : (sel == 1) ? g_K : g_V;

    __shared__ float As[64][36];
    __shared__ float Bs[32][DH];
    __shared__ int   ridx[64];
    int tid = threadIdx.x;
    if (tid < 64) {
        int lp = mbase + tid;
        ridx[tid] = g_list[t * M_ + (lp < mc ? lp : mc - 1)];
    }
    u64 acc2[4][4];
    #pragma unroll
    for (int i = 0; i < 4; i++)
        #pragma unroll
        for (int j = 0; j < 4; j++) acc2[i][j] = 0ull;
    int ty = tid >> 4, tx = tid & 15;
    int m0 = ty * 4, n0 = tx * 8;

    for (int k0 = 0; k0 < DH; k0 += 32) {
        __syncthreads();
        {
            int m = tid >> 3;
            int kk = (tid & 7) * 4;
            #pragma unroll
            for (int p = 0; p < 2; p++) {
                int mm = m + p * 32;
                float4 v = *(const float4*)(g_h + (size_t)(t * M_ + ridx[mm]) * DH + k0 + kk);
                As[mm][kk] = v.x; As[mm][kk + 1] = v.y; As[mm][kk + 2] = v.z; As[mm][kk + 3] = v.w;
            }
        }
        {
            float4* Bs4 = (float4*)Bs;
            const float4* W4 = (const float4*)(W + (size_t)k0 * DH);
            #pragma unroll
            for (int p = 0; p < 4; p++) Bs4[tid + p * 256] = W4[tid + p * 256];
        }
        __syncthreads();
        #pragma unroll
        for (int kk = 0; kk < 32; kk++) {
            u64 a0 = pack2(As[m0][kk]), a1 = pack2(As[m0 + 1][kk]);
            u64 a2 = pack2(As[m0 + 2][kk]), a3 = pack2(As[m0 + 3][kk]);
            ulonglong2 b0 = *(const ulonglong2*)&Bs[kk][n0];
            ulonglong2 b1 = *(const ulonglong2*)&Bs[kk][n0 + 4];
            ffma2(acc2[0][0], a0, b0.x); ffma2(acc2[0][1], a0, b0.y);
            ffma2(acc2[0][2], a0, b1.x); ffma2(acc2[0][3], a0, b1.y);
            ffma2(acc2[1][0], a1, b0.x); ffma2(acc2[1][1], a1, b0.y);
            ffma2(acc2[1][2], a1, b1.x); ffma2(acc2[1][3], a1, b1.y);
            ffma2(acc2[2][0], a2, b0.x); ffma2(acc2[2][1], a2, b0.y);
            ffma2(acc2[2][2], a2, b1.x); ffma2(acc2[2][3], a2, b1.y);
            ffma2(acc2[3][0], a3, b0.x); ffma2(acc2[3][1], a3, b0.y);
            ffma2(acc2[3][2], a3, b1.x); ffma2(acc2[3][3], a3, b1.y);
        }
    }
    float4 tb0 = *(const float4*)(tb + t * DH + n0);
    float4 tb1 = *(const float4*)(tb + t * DH + n0 + 4);
    #pragma unroll
    for (int i = 0; i < 4; i++) {
        int lp = mbase + m0 + i;
        if (lp < mc) {
            float* dst = out + (size_t)(t * M_ + lp) * DH + n0;
            float2 p0 = *(float2*)&acc2[i][0], p1 = *(float2*)&acc2[i][1];
            float2 p2 = *(float2*)&acc2[i][2], p3 = *(float2*)&acc2[i][3];
            float4 o0 = {p0.x + tb0.x, p0.y + tb0.y, p1.x + tb0.z, p1.y + tb0.w};
            float4 o1 = {p2.x + tb1.x, p2.y + tb1.y, p3.x + tb1.z, p3.y + tb1.w};
            *(float4*)dst = o0;
            *(float4*)(dst + 4) = o1;
        }
    }
}

__global__ void __launch_bounds__(256) k_out2(float* __restrict__ out) {
    int t = blockIdx.x;
    int mc = g_mcnt[t];
    int mbase = blockIdx.y * 64;
    if (mbase >= mc) return;
    __shared__ float As[64][36];
    __shared__ float Ws[32][DO];
    __shared__ int   ridx[64];
    int tid = threadIdx.x;
    if (tid < 64) {
        int lp = mbase + tid;
        ridx[tid] = g_list[t * M_ + (lp < mc ? lp : mc - 1)];
    }
    float acc[4][2];
    #pragma unroll
    for (int i = 0; i < 4; i++) { acc[i][0] = 0.0f; acc[i][1] = 0.0f; }
    int ty = tid >> 4, tx = tid & 15;
    int m0 = ty * 4, n0 = tx * 2;

    for (int k0 = 0; k0 < DH; k0 += 32) {
        __syncthreads();
        {
            int m = tid >> 3;
            int kk = (tid & 7) * 4;
            #pragma unroll
            for (int p = 0; p < 2; p++) {
                int mm = m + p * 32;
                int lp = mbase + mm;
                int lpc = (lp < mc ? lp : mc - 1);
                float4 v = *(const float4*)(g_agg + (size_t)(t * M_ + lpc) * DH + k0 + kk);
                As[mm][kk] = v.x; As[mm][kk + 1] = v.y; As[mm][kk + 2] = v.z; As[mm][kk + 3] = v.w;
            }
        }
        {
            float4* Ws4 = (float4*)Ws;
            const float4* W4 = (const float4*)(g_wc + (size_t)k0 * DO);
            Ws4[tid] = W4[tid];
        }
        __syncthreads();
        #pragma unroll
        for (int kk = 0; kk < 32; kk++) {
            float a0 = As[m0][kk], a1 = As[m0 + 1][kk], a2 = As[m0 + 2][kk], a3 = As[m0 + 3][kk];
            float2 b = *(float2*)&Ws[kk][n0];
            acc[0][0] += a0 * b.x; acc[0][1] += a0 * b.y;
            acc[1][0] += a1 * b.x; acc[1][1] += a1 * b.y;
            acc[2][0] += a2 * b.x; acc[2][1] += a2 * b.y;
            acc[3][0] += a3 * b.x; acc[3][1] += a3 * b.y;
        }
    }
    float2 bc = *(const float2*)(g_bc + n0);
    #pragma unroll
    for (int i = 0; i < 4; i++) {
        int lp = mbase + m0 + i;
        if (lp < mc) {
            int node = ridx[m0 + i];
            float2 o = {acc[i][0] + bc.x, acc[i][1] + bc.y};
            *(float2*)(out + ((size_t)node * T_ + t) * DO + n0) = o;
        }
    }
}

// ---------------- sparse aggregation + bias + ReLU ----------------
__global__ void k_spmm(const float* __restrict__ bias) {
    int t = blockIdx.x, lp = blockIdx.y;
    if (lp >= g_mcnt[t]) return;
    int i = g_list[t * M_ + lp];
    int f = threadIdx.x;
    float acc = g_z[(size_t)(t * M_ + i) * DH + f];
    const int* c8 = g_cnt8 + (t * M_ + i) * NJC;
    #pragma unroll
    for (int jc = 0; jc < NJC; jc++) {
        int c = c8[jc];
        const int* cl = g_col + ((size_t)((t * M_ + i) * NJC + jc)) * CAPC;
        for (int e = 0; e < c; e++) {
            int j = cl[e];
            acc += g_z[(size_t)(t * M_ + j) * DH + f];
        }
    }
    g_h[(size_t)(t * M_ + i) * DH + f] =
        fmaxf(g_nrm[t * M_ + i] * acc + bias[f], 0.0f);
}

// ---------------- flash attention: QT=64, tf32 mma.sync ----------------
#define QT 64
#define KC 64
#define QSTR 132      // Q smem row stride (floats) — conflict-free fragment loads
#define KSTR 132      // K/V smem row stride
#define SSTR 68       // score row stride
extern __shared__ float smattn[];
__global__ void __launch_bounds__(256) k_attn() {
    int t = blockIdx.x;
    int mc = g_mcnt[t];
    int qb = blockIdx.y * QT;
    if (qb >= mc) return;
    float* Qs   = smattn;                 // QT*QSTR
    float* Ks   = Qs + QT * QSTR;         // KC*KSTR (reused for V)
    float* S    = Ks + KC * KSTR;         // QT*SSTR
    float* rowm = S + QT * SSTR;          // QT
    float* rowl = rowm + QT;
    float* rowsc= rowl + QT;
    int tid = threadIdx.x;
    int w = tid >> 5, lane = tid & 31;
    int gID = lane >> 2, tig = lane & 3;
    int mq = (w & 3) * 16;                // q-tile base for this warp
    int dh = w >> 2;                      // 0/1: d-half (QK) / d-half (PV)
    int nv = min(QT, mc - qb);
    const float scl = 0.08838834764831845f;

    // Q fill (tf32-rounded)
    for (int p = 0; p < 8; p++) {
        int idx4 = tid + p * 256;
        int q = idx4 >> 5, d4 = (idx4 & 31) * 4;
        float4 v = {0.f, 0.f, 0.f, 0.f};
        if (q < nv) v = cvt_tf32_4(*(const float4*)(g_Q + (size_t)(t * M_ + qb + q) * DH + d4));
        *(float4*)(Qs + q * QSTR + d4) = v;
    }
    if (tid < QT) { rowm[tid] = -1e30f; rowl[tid] = 0.0f; }

    float o[8][4];                        // PV accumulators: 16q x 64d warp tile
    #pragma unroll
    for (int i = 0; i < 8; i++)
        #pragma unroll
        for (int j = 0; j < 4; j++) o[i][j] = 0.0f;

    for (int kb = 0; kb < mc; kb += KC) {
        int kn = min(KC, mc - kb);
        __syncthreads();
        // K fill (tf32-rounded)
        for (int p = 0; p < 8; p++) {
            int idx4 = tid + p * 256;
            int k = idx4 >> 5, d4 = (idx4 & 31) * 4;
            float4 v = {0.f, 0.f, 0.f, 0.f};
            if (k < kn) v = cvt_tf32_4(*(const float4*)(g_K + (size_t)(t * M_ + kb + k) * DH + d4));
            *(float4*)(Ks + k * KSTR + d4) = v;
        }
        __syncthreads();
        // QK scores: warp tile 16q x 64k over d-half (64 d), 8 nsub x 8 ksteps
        float c[8][4];
        #pragma unroll
        for (int i = 0; i < 8; i++)
            #pragma unroll
            for (int j = 0; j < 4; j++) c[i][j] = 0.0f;
        {
            int dbase = dh * 64;
            #pragma unroll
            for (int s = 0; s < 8; s++) {
                int d0 = dbase + s * 8;
                unsigned a0 = __float_as_uint(Qs[(mq + gID) * QSTR + d0 + tig]);
                unsigned a1 = __float_as_uint(Qs[(mq + gID + 8) * QSTR + d0 + tig]);
                unsigned a2 = __float_as_uint(Qs[(mq + gID) * QSTR + d0 + tig + 4]);
                unsigned a3 = __float_as_uint(Qs[(mq + gID + 8) * QSTR + d0 + tig + 4]);
                #pragma unroll
                for (int ns = 0; ns < 8; ns++) {
                    unsigned b0 = __float_as_uint(Ks[(ns * 8 + gID) * KSTR + d0 + tig]);
                    unsigned b1 = __float_as_uint(Ks[(ns * 8 + gID) * KSTR + d0 + tig + 4]);
                    mma_tf32(c[ns], a0, a1, a2, a3, b0, b1);
                }
            }
        }
        // combine d-halves deterministically: dh0 writes partials, dh1 adds+scales+masks
        if (dh == 0) {
            #pragma unroll
            for (int ns = 0; ns < 8; ns++) {
                int col = ns * 8 + 2 * tig;
                S[(mq + gID) * SSTR + col]     = c[ns][0];
                S[(mq + gID) * SSTR + col + 1] = c[ns][1];
                S[(mq + gID + 8) * SSTR + col]     = c[ns][2];
                S[(mq + gID + 8) * SSTR + col + 1] = c[ns][3];
            }
        }
        __syncthreads();
        if (dh == 1) {
            #pragma unroll
            for (int ns = 0; ns < 8; ns++) {
                int col = ns * 8 + 2 * tig;
                int r0 = (mq + gID) * SSTR, r1 = (mq + gID + 8) * SSTR;
                S[r0 + col]     = (col     < kn) ? (S[r0 + col]     + c[ns][0]) * scl : -1e30f;
                S[r0 + col + 1] = (col + 1 < kn) ? (S[r0 + col + 1] + c[ns][1]) * scl : -1e30f;
                S[r1 + col]     = (col     < kn) ? (S[r1 + col]     + c[ns][2]) * scl : -1e30f;
                S[r1 + col + 1] = (col + 1 < kn) ? (S[r1 + col + 1] + c[ns][3]) * scl : -1e30f;
            }
        }
        __syncthreads();
        // online softmax: 8 warps x 8 rows, 4 lanes per row; P stored tf32-rounded
        {
            int row = w * 8 + (lane >> 2);
            int l4 = lane & 3;
            float* Sr = S + row * SSTR;
            float mloc = -1e30f;
            for (int k = l4; k < KC; k += 4) mloc = fmaxf(mloc, Sr[k]);
            #pragma unroll
            for (int off = 2; off >= 1; off >>= 1)
                mloc = fmaxf(mloc, __shfl_xor_sync(0xffffffffu, mloc, off));
            float oldm = rowm[row];
            float newm = fmaxf(oldm, mloc);
            float ssum = 0.0f;
            for (int k = l4; k < KC; k += 4) {
                float p = cvt_tf32(__expf(Sr[k] - newm));
                Sr[k] = p;
                ssum += p;
            }
            #pragma unroll
            for (int off = 2; off >= 1; off >>= 1)
                ssum += __shfl_xor_sync(0xffffffffu, ssum, off);
            if (l4 == 0) {
                float sc = __expf(oldm - newm);
                rowsc[row] = sc;
                rowl[row] = rowl[row] * sc + ssum;
                rowm[row] = newm;
            }
        }
        __syncthreads();
        // rescale PV accumulators
        {
            float sc0 = rowsc[mq + gID];
            float sc1 = rowsc[mq + gID + 8];
            #pragma unroll
            for (int ns = 0; ns < 8; ns++) {
                o[ns][0] *= sc0; o[ns][1] *= sc0;
                o[ns][2] *= sc1; o[ns][3] *= sc1;
            }
        }
        // V fill (reuses Ks buffer, tf32-rounded)
        for (int p = 0; p < 8; p++) {
            int idx4 = tid + p * 256;
            int k = idx4 >> 5, d4 = (idx4 & 31) * 4;
            float4 v = {0.f, 0.f, 0.f, 0.f};
            if (k < kn) v = cvt_tf32_4(*(const float4*)(g_V + (size_t)(t * M_ + kb + k) * DH + d4));
            *(float4*)(Ks + k * KSTR + d4) = v;
        }
        __syncthreads();
        // PV: warp tile 16q x 64d (d-half dh), 8 nsub x 8 ksteps over KC
        {
            int dbase = dh * 64;
            #pragma unroll
            for (int s = 0; s < 8; s++) {
                int k0 = s * 8;
                unsigned a0 = __float_as_uint(S[(mq + gID) * SSTR + k0 + tig]);
                unsigned a1 = __float_as_uint(S[(mq + gID + 8) * SSTR + k0 + tig]);
                unsigned a2 = __float_as_uint(S[(mq + gID) * SSTR + k0 + tig + 4]);
                unsigned a3 = __float_as_uint(S[(mq + gID + 8) * SSTR + k0 + tig + 4]);
                #pragma unroll
                for (int ns = 0; ns < 8; ns++) {
                    int col = dbase + ns * 8 + gID;
                    unsigned b0 = __float_as_uint(Ks[(k0 + tig) * KSTR + col]);
                    unsigned b1 = __float_as_uint(Ks[(k0 + tig + 4) * KSTR + col]);
                    mma_tf32(o[ns], a0, a1, a2, a3, b0, b1);
                }
            }
        }
    }
    __syncthreads();
    // final normalize + store
    {
        int dbase = dh * 64;
        int r0 = mq + gID, r1 = mq + gID + 8;
        if (r0 < nv) {
            float inv = 1.0f / rowl[r0];
            float* dst = g_agg + (size_t)(t * M_ + qb + r0) * DH + dbase;
            #pragma unroll
            for (int ns = 0; ns < 8; ns++) {
                float2 v = {o[ns][0] * inv, o[ns][1] * inv};
                *(float2*)(dst + ns * 8 + 2 * tig) = v;
            }
        }
        if (r1 < nv) {
            float inv = 1.0f / rowl[r1];
            float* dst = g_agg + (size_t)(t * M_ + qb + r1) * DH + dbase;
            #pragma unroll
            for (int ns = 0; ns < 8; ns++) {
                float2 v = {o[ns][2] * inv, o[ns][3] * inv};
                *(float2*)(dst + ns * 8 + 2 * tig) = v;
            }
        }
    }
}

// ---------------- launch ----------------
extern "C" void kernel_launch(void* const* d_in, const int* in_sizes, int n_in,
                              void* d_out, int out_size) {
    const float* x   = (const float*)d_in[0];
    const float* A   = (const float*)d_in[1];
    const void*  em  = d_in[2];
    const float* w1  = (const float*)d_in[3];
    const float* b1  = (const float*)d_in[4];
    const float* w2  = (const float*)d_in[5];
    const float* b2  = (const float*)d_in[6];
    const float* tw  = (const float*)d_in[7];
    const float* tb  = (const float*)d_in[8];
    const float* qw  = (const float*)d_in[9];
    const float* qb  = (const float*)d_in[10];
    const float* kw  = (const float*)d_in[11];
    const float* kb  = (const float*)d_in[12];
    const float* vw  = (const float*)d_in[13];
    const float* vb  = (const float*)d_in[14];
    const float* ow  = (const float*)d_in[15];
    const float* ob  = (const float*)d_in[16];
    const float* fcw = (const float*)d_in[17];
    const float* fcb = (const float*)d_in[18];

    const int ATTN_SMEM = (QT * QSTR + KC * KSTR + QT * SSTR + 3 * QT) * 4; // 85760 B
    cudaFuncSetAttribute(k_attn, cudaFuncAttributeMaxDynamicSharedMemorySize, ATTN_SMEM);

    k_detect<<<1, 256>>>(em);
    k_mask<<<(T_ * M_) / 256, 256>>>(em);
    k_compact<<<T_, 1024>>>();
    k_edges<<<dim3(T_, NJC, M_ / 256), 256>>>(A);
    k_nrm<<<(T_ * M_) / 256, 256>>>();
    k_tbias<<<T_, DH>>>(tw, tb, qw, qb, kw, kb, vw, vb);
    k_comb<<<16, 256>>>(ow, ob, fcw, fcb);
    k_gemm_z<<<dim3(T_, M_ / 64), 256>>>(x, w1, 0);
    k_spmm<<<dim3(T_, M_), DH>>>(b1);
    k_gemm_z<<<dim3(T_, M_ / 64), 256>>>(nullptr, w2, 1);
    k_spmm<<<dim3(T_, M_), DH>>>(b2);
    k_gemm_qkv<<<dim3(T_, M_ / 64, 3), 256>>>(qw, kw, vw);
    k_attn<<<dim3(T_, M_ / QT), 256, ATTN_SMEM>>>();
    cudaMemsetAsync(d_out, 0, (size_t)out_size * sizeof(float));
    k_out2<<<dim3(T_, M_ / 64), 256>>>((float*)d_out);
}

// round 10
// speedup vs baseline: 1.8125x; 1.2026x over previous
#include <cuda_runtime.h>
#include <cuda_bf16.h>
#include <math.h>

#define T_  12
#define M_  2048
#define B_  2
#define N_  1024
#define DIN 64
#define DH  128
#define DT  16
#define DO  32
#define NJC 8
#define CAPC 32

// tf32 helpers
__device__ __forceinline__ float cvt_tf32(float f) {
    unsigned r;
    asm("cvt.rna.tf32.f32 %0, %1;" : "=r"(r) : "f"(f));
    return __uint_as_float(r);
}
__device__ __forceinline__ float4 cvt_tf32_4(float4 v) {
    v.x = cvt_tf32(v.x); v.y = cvt_tf32(v.y);
    v.z = cvt_tf32(v.z); v.w = cvt_tf32(v.w);
    return v;
}
__device__ __forceinline__ void mma_tf32(float* c,
                                         unsigned a0, unsigned a1, unsigned a2, unsigned a3,
                                         unsigned b0, unsigned b1) {
    asm("mma.sync.aligned.m16n8k8.row.col.f32.tf32.tf32.f32 "
        "{%0,%1,%2,%3}, {%4,%5,%6,%7}, {%8,%9}, {%0,%1,%2,%3};"
        : "+f"(c[0]), "+f"(c[1]), "+f"(c[2]), "+f"(c[3])
        : "r"(a0), "r"(a1), "r"(a2), "r"(a3), "r"(b0), "r"(b1));
}

// ---------------- device scratch ---------------
__device__ int   g_mdtype;
__device__ int   g_mask[T_ * M_];
__device__ int   g_list[T_ * M_];
__device__ int   g_mcnt[T_];
__device__ int   g_cnt8[T_ * M_ * NJC];
__device__ int   g_col [T_ * M_ * NJC * CAPC];
__device__ float g_nrm [T_ * M_];
__device__ float g_z   [T_ * M_ * DH];
__device__ float g_h   [T_ * M_ * DH];
__device__ float g_Q   [T_ * M_ * DH];
__device__ float g_K   [T_ * M_ * DH];
__device__ float g_V   [T_ * M_ * DH];
__device__ float g_agg [T_ * M_ * DH];
__device__ float g_qt  [T_ * DH];
__device__ float g_kt  [T_ * DH];
__device__ float g_vt  [T_ * DH];
__device__ float g_wc  [DH * DO];
__device__ float g_bc  [DO];

// ---------------- mask dtype detection ----------------
__global__ void k_detect(const void* p) {
    const int*   wi = (const int*)p;
    const float* wf = (const float*)p;
    int oki = 1, okf = 1;
    for (int r = 0; r < 8; r++) {
        int idx = r * 256 + threadIdx.x;
        int w  = wi[idx];
        float f = wf[idx];
        oki &= (w == 0 || w == 1);
        okf &= (f == 0.0f || f == 1.0f);
    }
    oki = __syncthreads_and(oki);
    okf = __syncthreads_and(okf);
    if (threadIdx.x == 0) g_mdtype = okf ? 2 : (oki ? 1 : 0);
}

__global__ void k_mask(const void* em) {
    int idx = blockIdx.x * 256 + threadIdx.x;
    int t = idx >> 11, m = idx & (M_ - 1);
    int b = m >> 10, n = m & (N_ - 1);
    int src = (b * T_ + t) * N_ + n;
    int dt = g_mdtype;
    int v;
    if (dt == 1)      v = ((const int*)em)[src] != 0;
    else if (dt == 2) v = ((const float*)em)[src] != 0.0f;
    else              v = ((const unsigned char*)em)[src] != 0;
    g_mask[idx] = v;
}

__global__ void __launch_bounds__(1024) k_compact() {
    int t = blockIdx.x, tid = threadIdx.x;
    __shared__ int wsum[32];
    __shared__ int sbase;
    if (tid == 0) sbase = 0;
    __syncthreads();
    for (int half = 0; half < 2; half++) {
        int i = half * 1024 + tid;
        int mv = g_mask[t * M_ + i];
        unsigned b = __ballot_sync(0xffffffffu, mv);
        int lane = tid & 31, wid = tid >> 5;
        if (lane == 0) wsum[wid] = __popc(b);
        __syncthreads();
        int woff = 0;
        for (int w = 0; w < wid; w++) woff += wsum[w];
        if (mv) g_list[t * M_ + sbase + woff + __popc(b & ((1u << lane) - 1u))] = i;
        __syncthreads();
        if (tid == 0) {
            int tot = 0;
            for (int w = 0; w < 32; w++) tot += wsum[w];
            sbase += tot;
        }
        __syncthreads();
    }
    if (tid == 0) g_mcnt[t] = sbase;
}

// streaming A scan (unconditional loads keep MLP high)
__global__ void k_edges(const float* __restrict__ A) {
    int t = blockIdx.x, jc = blockIdx.y, ic = blockIdx.z;
    int i = ic * 256 + threadIdx.x;
    __shared__ int mj[256];
    int jbase = jc * 256;
    mj[threadIdx.x] = g_mask[t * M_ + jbase + threadIdx.x];
    __syncthreads();
    int mi = g_mask[t * M_ + i];
    int cnt = 0;
    int* cols = g_col + ((size_t)((t * M_ + i) * NJC + jc)) * CAPC;
    if (mi) {
        const float* Ab = A + (size_t)(t * M_ + jbase) * M_ + i;
        #pragma unroll 8
        for (int jj = 0; jj < 256; jj++) {
            float a = Ab[(size_t)jj * M_];
            if (a != 0.0f && mj[jj] && cnt < CAPC) cols[cnt++] = jbase + jj;
        }
    }
    g_cnt8[(t * M_ + i) * NJC + jc] = cnt;
}

__global__ void k_nrm() {
    int idx = blockIdx.x * 256 + threadIdx.x;
    float nv = 0.0f;
    if (g_mask[idx]) {
        int c = 1;
        #pragma unroll
        for (int jc = 0; jc < NJC; jc++) c += g_cnt8[idx * NJC + jc];
        nv = rsqrtf((float)c);
    }
    g_nrm[idx] = nv;
}

__global__ void k_tbias(const float* __restrict__ tw, const float* __restrict__ tb,
                        const float* __restrict__ qw, const float* __restrict__ qb,
                        const float* __restrict__ kw, const float* __restrict__ kb,
                        const float* __restrict__ vw, const float* __restrict__ vb) {
    int t = blockIdx.x, f = threadIdx.x;
    float tv[DT];
    #pragma unroll
    for (int d = 0; d < DT; d++) tv[d] = sinf((float)t * tw[d] + tb[d]);
    float aq = qb[f], ak = kb[f], av = vb[f];
    #pragma unroll
    for (int d = 0; d < DT; d++) {
        aq += tv[d] * qw[(DH + d) * DH + f];
        ak += tv[d] * kw[(DH + d) * DH + f];
        av += tv[d] * vw[(DH + d) * DH + f];
    }
    g_qt[t * DH + f] = aq;
    g_kt[t * DH + f] = ak;
    g_vt[t * DH + f] = av;
}

__global__ void k_comb(const float* __restrict__ ow, const float* __restrict__ ob,
                       const float* __restrict__ fcw, const float* __restrict__ fcb) {
    int idx = blockIdx.x * 256 + threadIdx.x;
    int d = idx >> 5, f = idx & 31;
    float acc = 0.0f;
    #pragma unroll 8
    for (int e = 0; e < DH; e++) acc += ow[d * DH + e] * fcw[e * DO + f];
    g_wc[idx] = acc;
    if (idx < DO) {
        float b = fcb[idx];
        #pragma unroll 8
        for (int e = 0; e < DH; e++) b += ob[e] * fcw[e * DO + idx];
        g_bc[idx] = b;
    }
}

// ============ tf32 mma GEMM: 64 nodes x 128 features ============
// mode 0: src=x (K=64), out=g_z (by node), scaled by nrm
// mode 1: src=g_h (K=128), out=g_z (by node), scaled by nrm
#define WSTR 136
__global__ void __launch_bounds__(256) k_gemm_z(const float* __restrict__ xsrc,
                                                const float* __restrict__ W, int mode) {
    int t = blockIdx.x;
    int mc = g_mcnt[t];
    int mbase = blockIdx.y * 64;
    if (mbase >= mc) return;
    const float* src = (mode == 0) ? xsrc : (const float*)g_h;
    const int K = (mode == 0) ? DIN : DH;

    __shared__ float As[64][36];
    __shared__ float Ws[32][WSTR];
    __shared__ int   ridx[64];
    __shared__ float rn[64];
    int tid = threadIdx.x;
    if (tid < 64) {
        int lp = mbase + tid;
        int i = g_list[t * M_ + (lp < mc ? lp : mc - 1)];
        ridx[tid] = i;
        rn[tid] = g_nrm[t * M_ + i];
    }
    int w = tid >> 5, lane = tid & 31;
    int gID = lane >> 2, tig = lane & 3;
    int mq = (w & 3) * 16, nh = (w >> 2) * 64;

    float o[8][4];
    #pragma unroll
    for (int i = 0; i < 8; i++)
        #pragma unroll
        for (int j = 0; j < 4; j++) o[i][j] = 0.0f;

    for (int k0 = 0; k0 < K; k0 += 32) {
        __syncthreads();
        {   // A tile (gathered rows, tf32)
            int m = tid >> 3;
            int kk = (tid & 7) * 4;
            #pragma unroll
            for (int p = 0; p < 2; p++) {
                int mm = m + p * 32;
                float4 v = cvt_tf32_4(*(const float4*)(src + (size_t)(t * M_ + ridx[mm]) * K + k0 + kk));
                *(float4*)&As[mm][kk] = v;
            }
        }
        {   // W tile [32][128] -> Ws stride WSTR, tf32
            #pragma unroll
            for (int p = 0; p < 4; p++) {
                int idx4 = tid + p * 256;
                int row = idx4 >> 5, c4 = (idx4 & 31) * 4;
                float4 v = cvt_tf32_4(*(const float4*)(W + (size_t)(k0 + row) * DH + c4));
                *(float4*)&Ws[row][c4] = v;
            }
        }
        __syncthreads();
        #pragma unroll
        for (int s = 0; s < 4; s++) {
            int kk = s * 8;
            unsigned a0 = __float_as_uint(As[mq + gID][kk + tig]);
            unsigned a1 = __float_as_uint(As[mq + gID + 8][kk + tig]);
            unsigned a2 = __float_as_uint(As[mq + gID][kk + tig + 4]);
            unsigned a3 = __float_as_uint(As[mq + gID + 8][kk + tig + 4]);
            #pragma unroll
            for (int ns = 0; ns < 8; ns++) {
                int col = nh + ns * 8 + gID;
                unsigned b0 = __float_as_uint(Ws[kk + tig][col]);
                unsigned b1 = __float_as_uint(Ws[kk + tig + 4][col]);
                mma_tf32(o[ns], a0, a1, a2, a3, b0, b1);
            }
        }
    }
    int r0 = mq + gID, r1 = r0 + 8;
    if (mbase + r0 < mc) {
        float s = rn[r0];
        float* dst = g_z + (size_t)(t * M_ + ridx[r0]) * DH + nh;
        #pragma unroll
        for (int ns = 0; ns < 8; ns++) {
            float2 v = {o[ns][0] * s, o[ns][1] * s};
            *(float2*)(dst + ns * 8 + 2 * tig) = v;
        }
    }
    if (mbase + r1 < mc) {
        float s = rn[r1];
        float* dst = g_z + (size_t)(t * M_ + ridx[r1]) * DH + nh;
        #pragma unroll
        for (int ns = 0; ns < 8; ns++) {
            float2 v = {o[ns][2] * s, o[ns][3] * s};
            *(float2*)(dst + ns * 8 + 2 * tig) = v;
        }
    }
}

// QKV GEMM via tf32 mma: out compacted by lp, + per-t time bias; blockIdx.z selects weight
__global__ void __launch_bounds__(256) k_gemm_qkv(const float* __restrict__ qw,
                                                  const float* __restrict__ kw,
                                                  const float* __restrict__ vw) {
    int t = blockIdx.x;
    int mc = g_mcnt[t];
    int mbase = blockIdx.y * 64;
    if (mbase >= mc) return;
    int sel = blockIdx.z;
    const float* W  = (sel == 0) ? qw : (sel == 1) ? kw : vw;
    const float* tb = (sel == 0) ? g_qt : (sel == 1) ? g_kt : g_vt;
    float* out      = (sel == 0) ? g_Q : (sel == 1) ? g_K : g_V;

    __shared__ float As[64][36];
    __shared__ float Ws[32][WSTR];
    __shared__ int   ridx[64];
    int tid = threadIdx.x;
    if (tid < 64) {
        int lp = mbase + tid;
        ridx[tid] = g_list[t * M_ + (lp < mc ? lp : mc - 1)];
    }
    int w = tid >> 5, lane = tid & 31;
    int gID = lane >> 2, tig = lane & 3;
    int mq = (w & 3) * 16, nh = (w >> 2) * 64;

    float o[8][4];
    #pragma unroll
    for (int i = 0; i < 8; i++)
        #pragma unroll
        for (int j = 0; j < 4; j++) o[i][j] = 0.0f;

    for (int k0 = 0; k0 < DH; k0 += 32) {
        __syncthreads();
        {
            int m = tid >> 3;
            int kk = (tid & 7) * 4;
            #pragma unroll
            for (int p = 0; p < 2; p++) {
                int mm = m + p * 32;
                float4 v = cvt_tf32_4(*(const float4*)(g_h + (size_t)(t * M_ + ridx[mm]) * DH + k0 + kk));
                *(float4*)&As[mm][kk] = v;
            }
        }
        {
            #pragma unroll
            for (int p = 0; p < 4; p++) {
                int idx4 = tid + p * 256;
                int row = idx4 >> 5, c4 = (idx4 & 31) * 4;
                float4 v = cvt_tf32_4(*(const float4*)(W + (size_t)(k0 + row) * DH + c4));
                *(float4*)&Ws[row][c4] = v;
            }
        }
        __syncthreads();
        #pragma unroll
        for (int s = 0; s < 4; s++) {
            int kk = s * 8;
            unsigned a0 = __float_as_uint(As[mq + gID][kk + tig]);
            unsigned a1 = __float_as_uint(As[mq + gID + 8][kk + tig]);
            unsigned a2 = __float_as_uint(As[mq + gID][kk + tig + 4]);
            unsigned a3 = __float_as_uint(As[mq + gID + 8][kk + tig + 4]);
            #pragma unroll
            for (int ns = 0; ns < 8; ns++) {
                int col = nh + ns * 8 + gID;
                unsigned b0 = __float_as_uint(Ws[kk + tig][col]);
                unsigned b1 = __float_as_uint(Ws[kk + tig + 4][col]);
                mma_tf32(o[ns], a0, a1, a2, a3, b0, b1);
            }
        }
    }
    int r0 = mq + gID, r1 = r0 + 8;
    if (mbase + r0 < mc) {
        float* dst = out + (size_t)(t * M_ + mbase + r0) * DH + nh;
        #pragma unroll
        for (int ns = 0; ns < 8; ns++) {
            int c = ns * 8 + 2 * tig;
            float2 bv = *(const float2*)(tb + t * DH + nh + c);
            float2 v = {o[ns][0] + bv.x, o[ns][1] + bv.y};
            *(float2*)(dst + c) = v;
        }
    }
    if (mbase + r1 < mc) {
        float* dst = out + (size_t)(t * M_ + mbase + r1) * DH + nh;
        #pragma unroll
        for (int ns = 0; ns < 8; ns++) {
            int c = ns * 8 + 2 * tig;
            float2 bv = *(const float2*)(tb + t * DH + nh + c);
            float2 v = {o[ns][2] + bv.x, o[ns][3] + bv.y};
            *(float2*)(dst + c) = v;
        }
    }
}

__global__ void __launch_bounds__(256) k_out2(float* __restrict__ out) {
    int t = blockIdx.x;
    int mc = g_mcnt[t];
    int mbase = blockIdx.y * 64;
    if (mbase >= mc) return;
    __shared__ float As[64][36];
    __shared__ float Ws2[32][DO];
    __shared__ int   ridx[64];
    int tid = threadIdx.x;
    if (tid < 64) {
        int lp = mbase + tid;
        ridx[tid] = g_list[t * M_ + (lp < mc ? lp : mc - 1)];
    }
    float acc[4][2];
    #pragma unroll
    for (int i = 0; i < 4; i++) { acc[i][0] = 0.0f; acc[i][1] = 0.0f; }
    int ty = tid >> 4, tx = tid & 15;
    int m0 = ty * 4, n0 = tx * 2;

    for (int k0 = 0; k0 < DH; k0 += 32) {
        __syncthreads();
        {
            int m = tid >> 3;
            int kk = (tid & 7) * 4;
            #pragma unroll
            for (int p = 0; p < 2; p++) {
                int mm = m + p * 32;
                int lp = mbase + mm;
                int lpc = (lp < mc ? lp : mc - 1);
                float4 v = *(const float4*)(g_agg + (size_t)(t * M_ + lpc) * DH + k0 + kk);
                As[mm][kk] = v.x; As[mm][kk + 1] = v.y; As[mm][kk + 2] = v.z; As[mm][kk + 3] = v.w;
            }
        }
        {
            float4* Ws4 = (float4*)Ws2;
            const float4* W4 = (const float4*)(g_wc + (size_t)k0 * DO);
            Ws4[tid] = W4[tid];
        }
        __syncthreads();
        #pragma unroll
        for (int kk = 0; kk < 32; kk++) {
            float a0 = As[m0][kk], a1 = As[m0 + 1][kk], a2 = As[m0 + 2][kk], a3 = As[m0 + 3][kk];
            float2 b = *(float2*)&Ws2[kk][n0];
            acc[0][0] += a0 * b.x; acc[0][1] += a0 * b.y;
            acc[1][0] += a1 * b.x; acc[1][1] += a1 * b.y;
            acc[2][0] += a2 * b.x; acc[2][1] += a2 * b.y;
            acc[3][0] += a3 * b.x; acc[3][1] += a3 * b.y;
        }
    }
    float2 bc = *(const float2*)(g_bc + n0);
    #pragma unroll
    for (int i = 0; i < 4; i++) {
        int lp = mbase + m0 + i;
        if (lp < mc) {
            int node = ridx[m0 + i];
            float2 o = {acc[i][0] + bc.x, acc[i][1] + bc.y};
            *(float2*)(out + ((size_t)node * T_ + t) * DO + n0) = o;
        }
    }
}

// ---------------- sparse aggregation + bias + ReLU ----------------
__global__ void k_spmm(const float* __restrict__ bias) {
    int t = blockIdx.x, lp = blockIdx.y;
    if (lp >= g_mcnt[t]) return;
    int i = g_list[t * M_ + lp];
    int f = threadIdx.x;
    float acc = g_z[(size_t)(t * M_ + i) * DH + f];
    const int* c8 = g_cnt8 + (t * M_ + i) * NJC;
    #pragma unroll
    for (int jc = 0; jc < NJC; jc++) {
        int c = c8[jc];
        const int* cl = g_col + ((size_t)((t * M_ + i) * NJC + jc)) * CAPC;
        for (int e = 0; e < c; e++) {
            int j = cl[e];
            acc += g_z[(size_t)(t * M_ + j) * DH + f];
        }
    }
    g_h[(size_t)(t * M_ + i) * DH + f] =
        fmaxf(g_nrm[t * M_ + i] * acc + bias[f], 0.0f);
}

// ---------------- flash attention: QT=64, tf32 mma.sync ----------------
#define QT 64
#define KC 64
#define QSTR 132      // Q smem row stride — QK A-frag conflict-free (≡4 mod 32)
#define KSTR 132      // K row stride — QK B-frag conflict-free (≡4)
#define VSTR 136      // V row stride — PV B-frag conflict-free (≡8)
#define SSTR 68       // score row stride (≡4)
extern __shared__ float smattn[];
__global__ void __launch_bounds__(256) k_attn() {
    int t = blockIdx.x;
    int mc = g_mcnt[t];
    int qb = blockIdx.y * QT;
    if (qb >= mc) return;
    float* Qs   = smattn;                 // QT*QSTR
    float* Ks   = Qs + QT * QSTR;         // KC*VSTR buffer (K uses stride KSTR, V uses VSTR)
    float* S    = Ks + KC * VSTR;         // QT*SSTR
    float* rowm = S + QT * SSTR;          // QT
    float* rowl = rowm + QT;
    float* rowsc= rowl + QT;
    int tid = threadIdx.x;
    int w = tid >> 5, lane = tid & 31;
    int gID = lane >> 2, tig = lane & 3;
    int mq = (w & 3) * 16;
    int dh = w >> 2;
    int nv = min(QT, mc - qb);
    const float scl = 0.08838834764831845f;

    // Q fill (tf32-rounded)
    for (int p = 0; p < 8; p++) {
        int idx4 = tid + p * 256;
        int q = idx4 >> 5, d4 = (idx4 & 31) * 4;
        float4 v = {0.f, 0.f, 0.f, 0.f};
        if (q < nv) v = cvt_tf32_4(*(const float4*)(g_Q + (size_t)(t * M_ + qb + q) * DH + d4));
        *(float4*)(Qs + q * QSTR + d4) = v;
    }
    if (tid < QT) { rowm[tid] = -1e30f; rowl[tid] = 0.0f; }

    float o[8][4];
    #pragma unroll
    for (int i = 0; i < 8; i++)
        #pragma unroll
        for (int j = 0; j < 4; j++) o[i][j] = 0.0f;

    for (int kb = 0; kb < mc; kb += KC) {
        int kn = min(KC, mc - kb);
        __syncthreads();
        // K fill (stride KSTR, tf32)
        for (int p = 0; p < 8; p++) {
            int idx4 = tid + p * 256;
            int k = idx4 >> 5, d4 = (idx4 & 31) * 4;
            float4 v = {0.f, 0.f, 0.f, 0.f};
            if (k < kn) v = cvt_tf32_4(*(const float4*)(g_K + (size_t)(t * M_ + kb + k) * DH + d4));
            *(float4*)(Ks + k * KSTR + d4) = v;
        }
        __syncthreads();
        // QK scores: warp tile 16q x 64k over d-half
        float c[8][4];
        #pragma unroll
        for (int i = 0; i < 8; i++)
            #pragma unroll
            for (int j = 0; j < 4; j++) c[i][j] = 0.0f;
        {
            int dbase = dh * 64;
            #pragma unroll
            for (int s = 0; s < 8; s++) {
                int d0 = dbase + s * 8;
                unsigned a0 = __float_as_uint(Qs[(mq + gID) * QSTR + d0 + tig]);
                unsigned a1 = __float_as_uint(Qs[(mq + gID + 8) * QSTR + d0 + tig]);
                unsigned a2 = __float_as_uint(Qs[(mq + gID) * QSTR + d0 + tig + 4]);
                unsigned a3 = __float_as_uint(Qs[(mq + gID + 8) * QSTR + d0 + tig + 4]);
                #pragma unroll
                for (int ns = 0; ns < 8; ns++) {
                    unsigned b0 = __float_as_uint(Ks[(ns * 8 + gID) * KSTR + d0 + tig]);
                    unsigned b1 = __float_as_uint(Ks[(ns * 8 + gID) * KSTR + d0 + tig + 4]);
                    mma_tf32(c[ns], a0, a1, a2, a3, b0, b1);
                }
            }
        }
        // combine d-halves deterministically
        if (dh == 0) {
            #pragma unroll
            for (int ns = 0; ns < 8; ns++) {
                int col = ns * 8 + 2 * tig;
                S[(mq + gID) * SSTR + col]     = c[ns][0];
                S[(mq + gID) * SSTR + col + 1] = c[ns][1];
                S[(mq + gID + 8) * SSTR + col]     = c[ns][2];
                S[(mq + gID + 8) * SSTR + col + 1] = c[ns][3];
            }
        }
        __syncthreads();
        if (dh == 1) {
            #pragma unroll
            for (int ns = 0; ns < 8; ns++) {
                int col = ns * 8 + 2 * tig;
                int r0 = (mq + gID) * SSTR, r1 = (mq + gID + 8) * SSTR;
                S[r0 + col]     = (col     < kn) ? (S[r0 + col]     + c[ns][0]) * scl : -1e30f;
                S[r0 + col + 1] = (col + 1 < kn) ? (S[r0 + col + 1] + c[ns][1]) * scl : -1e30f;
                S[r1 + col]     = (col     < kn) ? (S[r1 + col]     + c[ns][2]) * scl : -1e30f;
                S[r1 + col + 1] = (col + 1 < kn) ? (S[r1 + col + 1] + c[ns][3]) * scl : -1e30f;
            }
        }
        __syncthreads();
        // online softmax: 8 warps x 8 rows, 4 lanes per row; P stored tf32-rounded
        {
            int row = w * 8 + (lane >> 2);
            int l4 = lane & 3;
            float* Sr = S + row * SSTR;
            float mloc = -1e30f;
            for (int k = l4; k < KC; k += 4) mloc = fmaxf(mloc, Sr[k]);
            #pragma unroll
            for (int off = 2; off >= 1; off >>= 1)
                mloc = fmaxf(mloc, __shfl_xor_sync(0xffffffffu, mloc, off));
            float oldm = rowm[row];
            float newm = fmaxf(oldm, mloc);
            float ssum = 0.0f;
            for (int k = l4; k < KC; k += 4) {
                float p = cvt_tf32(__expf(Sr[k] - newm));
                Sr[k] = p;
                ssum += p;
            }
            #pragma unroll
            for (int off = 2; off >= 1; off >>= 1)
                ssum += __shfl_xor_sync(0xffffffffu, ssum, off);
            if (l4 == 0) {
                float sc = __expf(oldm - newm);
                rowsc[row] = sc;
                rowl[row] = rowl[row] * sc + ssum;
                rowm[row] = newm;
            }
        }
        __syncthreads();
        // rescale PV accumulators
        {
            float sc0 = rowsc[mq + gID];
            float sc1 = rowsc[mq + gID + 8];
            #pragma unroll
            for (int ns = 0; ns < 8; ns++) {
                o[ns][0] *= sc0; o[ns][1] *= sc0;
                o[ns][2] *= sc1; o[ns][3] *= sc1;
            }
        }
        // V fill (stride VSTR, tf32)
        for (int p = 0; p < 8; p++) {
            int idx4 = tid + p * 256;
            int k = idx4 >> 5, d4 = (idx4 & 31) * 4;
            float4 v = {0.f, 0.f, 0.f, 0.f};
            if (k < kn) v = cvt_tf32_4(*(const float4*)(g_V + (size_t)(t * M_ + kb + k) * DH + d4));
            *(float4*)(Ks + k * VSTR + d4) = v;
        }
        __syncthreads();
        // PV: warp tile 16q x 64d (d-half dh)
        {
            int dbase = dh * 64;
            #pragma unroll
            for (int s = 0; s < 8; s++) {
                int k0 = s * 8;
                unsigned a0 = __float_as_uint(S[(mq + gID) * SSTR + k0 + tig]);
                unsigned a1 = __float_as_uint(S[(mq + gID + 8) * SSTR + k0 + tig]);
                unsigned a2 = __float_as_uint(S[(mq + gID) * SSTR + k0 + tig + 4]);
                unsigned a3 = __float_as_uint(S[(mq + gID + 8) * SSTR + k0 + tig + 4]);
                #pragma unroll
                for (int ns = 0; ns < 8; ns++) {
                    int col = dbase + ns * 8 + gID;
                    unsigned b0 = __float_as_uint(Ks[(k0 + tig) * VSTR + col]);
                    unsigned b1 = __float_as_uint(Ks[(k0 + tig + 4) * VSTR + col]);
                    mma_tf32(o[ns], a0, a1, a2, a3, b0, b1);
                }
            }
        }
    }
    __syncthreads();
    // final normalize + store
    {
        int dbase = dh * 64;
        int r0 = mq + gID, r1 = mq + gID + 8;
        if (r0 < nv) {
            float inv = 1.0f / rowl[r0];
            float* dst = g_agg + (size_t)(t * M_ + qb + r0) * DH + dbase;
            #pragma unroll
            for (int ns = 0; ns < 8; ns++) {
                float2 v = {o[ns][0] * inv, o[ns][1] * inv};
                *(float2*)(dst + ns * 8 + 2 * tig) = v;
            }
        }
        if (r1 < nv) {
            float inv = 1.0f / rowl[r1];
            float* dst = g_agg + (size_t)(t * M_ + qb + r1) * DH + dbase;
            #pragma unroll
            for (int ns = 0; ns < 8; ns++) {
                float2 v = {o[ns][2] * inv, o[ns][3] * inv};
                *(float2*)(dst + ns * 8 + 2 * tig) = v;
            }
        }
    }
}

// ---------------- launch ----------------
extern "C" void kernel_launch(void* const* d_in, const int* in_sizes, int n_in,
                              void* d_out, int out_size) {
    const float* x   = (const float*)d_in[0];
    const float* A   = (const float*)d_in[1];
    const void*  em  = d_in[2];
    const float* w1  = (const float*)d_in[3];
    const float* b1  = (const float*)d_in[4];
    const float* w2  = (const float*)d_in[5];
    const float* b2  = (const float*)d_in[6];
    const float* tw  = (const float*)d_in[7];
    const float* tb  = (const float*)d_in[8];
    const float* qw  = (const float*)d_in[9];
    const float* qb  = (const float*)d_in[10];
    const float* kw  = (const float*)d_in[11];
    const float* kb  = (const float*)d_in[12];
    const float* vw  = (const float*)d_in[13];
    const float* vb  = (const float*)d_in[14];
    const float* ow  = (const float*)d_in[15];
    const float* ob  = (const float*)d_in[16];
    const float* fcw = (const float*)d_in[17];
    const float* fcb = (const float*)d_in[18];

    const int ATTN_SMEM = (QT * QSTR + KC * VSTR + QT * SSTR + 3 * QT) * 4; // 86784 B
    cudaFuncSetAttribute(k_attn, cudaFuncAttributeMaxDynamicSharedMemorySize, ATTN_SMEM);

    k_detect<<<1, 256>>>(em);
    k_mask<<<(T_ * M_) / 256, 256>>>(em);
    k_compact<<<T_, 1024>>>();
    k_edges<<<dim3(T_, NJC, M_ / 256), 256>>>(A);
    k_nrm<<<(T_ * M_) / 256, 256>>>();
    k_tbias<<<T_, DH>>>(tw, tb, qw, qb, kw, kb, vw, vb);
    k_comb<<<16, 256>>>(ow, ob, fcw, fcb);
    k_gemm_z<<<dim3(T_, M_ / 64), 256>>>(x, w1, 0);
    k_spmm<<<dim3(T_, M_), DH>>>(b1);
    k_gemm_z<<<dim3(T_, M_ / 64), 256>>>(nullptr, w2, 1);
    k_spmm<<<dim3(T_, M_), DH>>>(b2);
    k_gemm_qkv<<<dim3(T_, M_ / 64, 3), 256>>>(qw, kw, vw);
    k_attn<<<dim3(T_, M_ / QT), 256, ATTN_SMEM>>>();
    cudaMemsetAsync(d_out, 0, (size_t)out_size * sizeof(float));
    k_out2<<<dim3(T_, M_ / 64), 256>>>((float*)d_out);
}